// round 12
// baseline (speedup 1.0000x reference)
#include <cuda_runtime.h>
#include <cstdint>
#include <math.h>

// Causal self-attention, B=4, S=4096, D=64, fp32.
// Tensor-core flash attention (mma.sync m16n8k8 tf32) + 4-way split-K.
// R12: R10 tiling (BMM=128, 4 warps x 32 rows) + cp.async double-buffered
// K/V in XOR-swizzled linear layouts; one __syncthreads per tile.

#define BB 4
#define SS 4096
#define DHH 64
#define BMM 128
#define NTHREADS 128
#define SPLITS 4
#define NROWS (BB * SS)

// smem (floats): K 2x4096, V 2x4096, Q frag table 4x2048, P 4x1024.
#define OFF_K 0
#define OFF_V 8192
#define OFF_QF 16384
#define OFF_P 24576
#define SMEM_FLOATS 28672
#define SMEM_BYTES (SMEM_FLOATS * 4)

__device__ float g_pO[SPLITS * NROWS * DHH];
__device__ float g_ml[SPLITS * NROWS * 2];

__device__ __forceinline__ float ex2a(float x) {
    float y; asm("ex2.approx.f32 %0,%1;" : "=f"(y) : "f"(x)); return y;
}
__device__ __forceinline__ void split2(float f, float& hi, float& lo) {
    hi = __uint_as_float(__float_as_uint(f) & 0xffffe000u);
    lo = f - hi;
}
__device__ __forceinline__ float tf32_rna(float x) {
    unsigned y;
    asm("cvt.rna.tf32.f32 %0, %1;" : "=r"(y) : "f"(x));
    return __uint_as_float(y);
}
__device__ __forceinline__ void cp16(unsigned dst, const void* src) {
    asm volatile("cp.async.ca.shared.global [%0], [%1], 16;" :: "r"(dst), "l"(src));
}
__device__ __forceinline__ void cp4(unsigned dst, const void* src) {
    asm volatile("cp.async.ca.shared.global [%0], [%1], 4;" :: "r"(dst), "l"(src));
}
__device__ __forceinline__ void cp_commit() {
    asm volatile("cp.async.commit_group;");
}
__device__ __forceinline__ void cp_wait0() {
    asm volatile("cp.async.wait_group 0;");
}

__device__ __forceinline__ void mma_tf32(float c[4],
        float a0, float a1, float a2, float a3, float b0, float b1) {
    asm("mma.sync.aligned.m16n8k8.row.col.f32.tf32.tf32.f32 "
        "{%0,%1,%2,%3},{%4,%5,%6,%7},{%8,%9},{%0,%1,%2,%3};"
        : "+f"(c[0]), "+f"(c[1]), "+f"(c[2]), "+f"(c[3])
        : "r"(__float_as_uint(a0)), "r"(__float_as_uint(a1)),
          "r"(__float_as_uint(a2)), "r"(__float_as_uint(a3)),
          "r"(__float_as_uint(b0)), "r"(__float_as_uint(b1)));
}
__device__ __forceinline__ void mma3(float c[4],
        const float ah[4], const float al[4],
        float bh0, float bh1, float bl0, float bl1) {
    mma_tf32(c, ah[0], ah[1], ah[2], ah[3], bh0, bh1);
    mma_tf32(c, al[0], al[1], al[2], al[3], bh0, bh1);
    mma_tf32(c, ah[0], ah[1], ah[2], ah[3], bl0, bl1);
}
__device__ __forceinline__ void split4(const float4& v, float h[4], float l[4]) {
    split2(v.x, h[0], l[0]); split2(v.y, h[1], l[1]);
    split2(v.z, h[2], l[2]); split2(v.w, h[3], l[3]);
}

__global__ __launch_bounds__(NTHREADS, 2)
void fa_mma_split(const float* __restrict__ Q, const float* __restrict__ K,
                  const float* __restrict__ V) {
    extern __shared__ float sm[];
    const unsigned smb = (unsigned)__cvta_generic_to_shared(sm);
    const int idx   = blockIdx.x;
    const int split = idx & (SPLITS - 1);
    const int rest  = idx >> 2;
    const int b     = rest & 3;
    const int qt    = (SS / BMM) - 1 - (rest >> 2);   // heavy q-tiles first
    const int tid   = threadIdx.x;
    const int wid   = tid >> 5;
    const int lane  = tid & 31;
    const int gg    = lane >> 2;
    const int c4    = lane & 3;
    const int rA0 = qt * BMM + wid * 32 + gg;
    const int rA1 = rA0 + 8;
    const int rB0 = rA0 + 16;
    const int rB1 = rA0 + 24;

    float* po  = g_pO + ((size_t)split * NROWS) * DHH;
    float* pml = g_ml + ((size_t)split * NROWS) * 2;
    const int rowg_cta = b * SS + qt * BMM;

    const int ntile = 2 * qt + 2;
    const int len = (ntile + SPLITS - 1) / SPLITS;
    const int t0  = split * len;
    const int t1  = min(t0 + len, ntile);

    if (t0 >= t1) {   // empty split: neutral partials
        for (int i = tid; i < BMM * DHH; i += NTHREADS)
            po[(size_t)(rowg_cta + (i >> 6)) * DHH + (i & 63)] = 0.f;
        pml[(size_t)(rowg_cta + tid) * 2 + 0] = -INFINITY;
        pml[(size_t)(rowg_cta + tid) * 2 + 1] = 0.f;
        return;
    }

    // ---- stage Q raw into K-buffer scratch, build per-warp Q frag table
    {
        const float4* qg4 = (const float4*)(Q + ((size_t)b * SS + qt * BMM) * DHH);
        float4* qs4 = (float4*)sm;
#pragma unroll
        for (int i = 0; i < 16; i++) qs4[i * NTHREADS + tid] = qg4[i * NTHREADS + tid];
        __syncthreads();
        const float qscale = 0.125f * 1.44269504088896f;  // 1/sqrt(64)*log2(e)
        const int lA = wid * 32 + gg, lB = lA + 16;
        float* qf = sm + OFF_QF + wid * 2048;
#pragma unroll
        for (int t = 0; t < 8; t++) {
            float4 a, bq;
            a.x  = sm[lA * 64 + 8 * t + c4]            * qscale;
            a.y  = sm[(lA + 8) * 64 + 8 * t + c4]      * qscale;
            a.z  = sm[lA * 64 + 8 * t + c4 + 4]        * qscale;
            a.w  = sm[(lA + 8) * 64 + 8 * t + c4 + 4]  * qscale;
            bq.x = sm[lB * 64 + 8 * t + c4]            * qscale;
            bq.y = sm[(lB + 8) * 64 + 8 * t + c4]      * qscale;
            bq.z = sm[lB * 64 + 8 * t + c4 + 4]        * qscale;
            bq.w = sm[(lB + 8) * 64 + 8 * t + c4 + 4]  * qscale;
            *(float4*)&qf[t * 256 + lane * 4]       = a;
            *(float4*)&qf[t * 256 + 128 + lane * 4] = bq;
        }
        __syncthreads();   // scratch free; K buffers may now be filled
    }

    const float* Kg = K + (size_t)b * SS * DHH;
    const float* Vg = V + (size_t)b * SS * DHH;

    // prefetch helper expanded inline twice (prologue + loop)
#define PREFETCH(kt_, buf_) do {                                               \
        const float* kg = Kg + (size_t)(kt_) * 64 * DHH;                       \
        const float* vg = Vg + (size_t)(kt_) * 64 * DHH;                       \
        unsigned kb = smb + (unsigned)(OFF_K + (buf_) * 4096) * 4u;            \
        unsigned vb = smb + (unsigned)(OFF_V + (buf_) * 4096) * 4u;            \
        _Pragma("unroll")                                                      \
        for (int i = 0; i < 8; i++) {                                          \
            int e = i * NTHREADS + tid;                                        \
            int row = e >> 4, dq = e & 15;                                     \
            cp16(kb + (unsigned)(row * 64 + 4 * (dq ^ (row & 7))) * 4u,        \
                 kg + row * 64 + dq * 4);                                      \
        }                                                                      \
        _Pragma("unroll")                                                      \
        for (int i = 0; i < 8; i++) {                                          \
            int e = i * NTHREADS + tid;                                        \
            int n = e >> 4, dbase = (e & 15) << 2;                             \
            _Pragma("unroll")                                                  \
            for (int jj = 0; jj < 4; jj++) {                                   \
                int d = dbase + jj;                                            \
                cp4(vb + (unsigned)(d * 64 + (n ^ ((d & 7) << 2))) * 4u,       \
                    vg + n * 64 + d);                                          \
            }                                                                  \
        }                                                                      \
        cp_commit();                                                           \
    } while (0)

    PREFETCH(t0, 0);

    float oA[8][4], oB[8][4];
#pragma unroll
    for (int nn = 0; nn < 8; nn++)
#pragma unroll
        for (int c = 0; c < 4; c++) { oA[nn][c] = 0.f; oB[nn][c] = 0.f; }
    float mA0 = -INFINITY, mA1 = -INFINITY, mB0 = -INFINITY, mB1 = -INFINITY;
    float lA0 = 0.f, lA1 = 0.f, lB0 = 0.f, lB1 = 0.f;

    for (int kt = t0; kt < t1; kt++) {
        const bool masked = (kt >= 2 * qt);
        const int cur = (kt - t0) & 1;

        cp_wait0();
        __syncthreads();                     // buf[cur] ready; buf[cur^1] free
        if (kt + 1 < t1) PREFETCH(kt + 1, cur ^ 1);

        const float* kb = sm + OFF_K + cur * 4096;
        const float* vb = sm + OFF_V + cur * 4096;

        // ---- S = Q K^T (K from swizzled linear layout, 4x LDS.32 per frag)
        float sA[8][4], sB[8][4];
#pragma unroll
        for (int nn = 0; nn < 8; nn++)
#pragma unroll
            for (int c = 0; c < 4; c++) { sA[nn][c] = 0.f; sB[nn][c] = 0.f; }
        const float* qf = sm + OFF_QF + wid * 2048;
#pragma unroll
        for (int u = 0; u < 4; u++) {
            float4 q0A = *(const float4*)&qf[(2 * u) * 256 + lane * 4];
            float4 q0B = *(const float4*)&qf[(2 * u) * 256 + 128 + lane * 4];
            float4 q1A = *(const float4*)&qf[(2 * u + 1) * 256 + lane * 4];
            float4 q1B = *(const float4*)&qf[(2 * u + 1) * 256 + 128 + lane * 4];
            float q0Ah[4], q0Al[4], q0Bh[4], q0Bl[4];
            float q1Ah[4], q1Al[4], q1Bh[4], q1Bl[4];
            split4(q0A, q0Ah, q0Al); split4(q0B, q0Bh, q0Bl);
            split4(q1A, q1Ah, q1Al); split4(q1B, q1Bh, q1Bl);
#pragma unroll
            for (int nn = 0; nn < 8; nn++) {
                int krow = nn * 8 + gg;
                int kbase = krow * 64 + c4;
                int sw = krow & 7;
                float4 kr;
                kr.x = kb[kbase + 4 * ((4 * u + 0) ^ sw)];
                kr.y = kb[kbase + 4 * ((4 * u + 1) ^ sw)];
                kr.z = kb[kbase + 4 * ((4 * u + 2) ^ sw)];
                kr.w = kb[kbase + 4 * ((4 * u + 3) ^ sw)];
                float kh[4], kl[4];
                split4(kr, kh, kl);
                mma3(sA[nn], q0Ah, q0Al, kh[0], kh[1], kl[0], kl[1]);
                mma3(sA[nn], q1Ah, q1Al, kh[2], kh[3], kl[2], kl[3]);
                mma3(sB[nn], q0Bh, q0Bl, kh[0], kh[1], kl[0], kl[1]);
                mma3(sB[nn], q1Bh, q1Bl, kh[2], kh[3], kl[2], kl[3]);
            }
        }

        if (masked) {
#pragma unroll
            for (int nn = 0; nn < 8; nn++) {
                int kbk = kt * 64 + nn * 8 + 2 * c4;
                if (kbk     > rA0) sA[nn][0] = -1e30f;
                if (kbk + 1 > rA0) sA[nn][1] = -1e30f;
                if (kbk     > rA1) sA[nn][2] = -1e30f;
                if (kbk + 1 > rA1) sA[nn][3] = -1e30f;
                if (kbk     > rB0) sB[nn][0] = -1e30f;
                if (kbk + 1 > rB0) sB[nn][1] = -1e30f;
                if (kbk     > rB1) sB[nn][2] = -1e30f;
                if (kbk + 1 > rB1) sB[nn][3] = -1e30f;
            }
        }

        // ---- online softmax for 4 row groups
        float x0 = sA[0][0], x1 = sA[0][2], x2 = sB[0][0], x3 = sB[0][2];
#pragma unroll
        for (int nn = 0; nn < 8; nn++) {
            x0 = fmaxf(x0, fmaxf(sA[nn][0], sA[nn][1]));
            x1 = fmaxf(x1, fmaxf(sA[nn][2], sA[nn][3]));
            x2 = fmaxf(x2, fmaxf(sB[nn][0], sB[nn][1]));
            x3 = fmaxf(x3, fmaxf(sB[nn][2], sB[nn][3]));
        }
        x0 = fmaxf(x0, __shfl_xor_sync(0xffffffffu, x0, 1));
        x0 = fmaxf(x0, __shfl_xor_sync(0xffffffffu, x0, 2));
        x1 = fmaxf(x1, __shfl_xor_sync(0xffffffffu, x1, 1));
        x1 = fmaxf(x1, __shfl_xor_sync(0xffffffffu, x1, 2));
        x2 = fmaxf(x2, __shfl_xor_sync(0xffffffffu, x2, 1));
        x2 = fmaxf(x2, __shfl_xor_sync(0xffffffffu, x2, 2));
        x3 = fmaxf(x3, __shfl_xor_sync(0xffffffffu, x3, 1));
        x3 = fmaxf(x3, __shfl_xor_sync(0xffffffffu, x3, 2));
        float nA0 = fmaxf(mA0, x0), nA1 = fmaxf(mA1, x1);
        float nB0 = fmaxf(mB0, x2), nB1 = fmaxf(mB1, x3);
        float cA0 = ex2a(mA0 - nA0), cA1 = ex2a(mA1 - nA1);
        float cB0 = ex2a(mB0 - nB0), cB1 = ex2a(mB1 - nB1);
        mA0 = nA0; mA1 = nA1; mB0 = nB0; mB1 = nB1;
        lA0 *= cA0; lA1 *= cA1; lB0 *= cB0; lB1 *= cB1;
        float uA0 = 0.f, uA1 = 0.f, uB0 = 0.f, uB1 = 0.f;
#pragma unroll
        for (int nn = 0; nn < 8; nn++) {
            sA[nn][0] = tf32_rna(ex2a(sA[nn][0] - mA0));
            sA[nn][1] = tf32_rna(ex2a(sA[nn][1] - mA0));
            sA[nn][2] = tf32_rna(ex2a(sA[nn][2] - mA1));
            sA[nn][3] = tf32_rna(ex2a(sA[nn][3] - mA1));
            sB[nn][0] = tf32_rna(ex2a(sB[nn][0] - mB0));
            sB[nn][1] = tf32_rna(ex2a(sB[nn][1] - mB0));
            sB[nn][2] = tf32_rna(ex2a(sB[nn][2] - mB1));
            sB[nn][3] = tf32_rna(ex2a(sB[nn][3] - mB1));
            uA0 += sA[nn][0] + sA[nn][1];
            uA1 += sA[nn][2] + sA[nn][3];
            uB0 += sB[nn][0] + sB[nn][1];
            uB1 += sB[nn][2] + sB[nn][3];
            oA[nn][0] *= cA0; oA[nn][1] *= cA0;
            oA[nn][2] *= cA1; oA[nn][3] *= cA1;
            oB[nn][0] *= cB0; oB[nn][1] *= cB0;
            oB[nn][2] *= cB1; oB[nn][3] *= cB1;
        }
        uA0 += __shfl_xor_sync(0xffffffffu, uA0, 1);
        uA0 += __shfl_xor_sync(0xffffffffu, uA0, 2);
        uA1 += __shfl_xor_sync(0xffffffffu, uA1, 1);
        uA1 += __shfl_xor_sync(0xffffffffu, uA1, 2);
        uB0 += __shfl_xor_sync(0xffffffffu, uB0, 1);
        uB0 += __shfl_xor_sync(0xffffffffu, uB0, 2);
        uB1 += __shfl_xor_sync(0xffffffffu, uB1, 1);
        uB1 += __shfl_xor_sync(0xffffffffu, uB1, 2);
        lA0 += uA0; lA1 += uA1; lB0 += uB0; lB1 += uB1;

        // ---- PV in two key-halves through the per-warp P region
        float* wP = sm + OFF_P + wid * 1024;
#pragma unroll
        for (int h = 0; h < 2; h++) {
#pragma unroll
            for (int kkl = 0; kkl < 4; kkl++) {
                int nn = 4 * h + kkl;
#pragma unroll
                for (int ci = 0; ci < 4; ci++) {
                    int cc   = 2 * c4 + (ci & 1);
                    int slot = ((cc >= 4) ? 2 : 0) + ((ci >= 2) ? 1 : 0);
                    int lamp = gg * 4 + (cc & 3);
                    wP[kkl * 256 + lamp * 4 + slot]       = sA[nn][ci];
                    wP[kkl * 256 + 128 + lamp * 4 + slot] = sB[nn][ci];
                }
            }
            __syncwarp();
#pragma unroll
            for (int kkl = 0; kkl < 4; kkl++) {
                float4 pA = *(const float4*)&wP[kkl * 256 + lane * 4];
                float4 pB = *(const float4*)&wP[kkl * 256 + 128 + lane * 4];
                int kk = 4 * h + kkl;
                int nb = kk * 8 + c4;
#pragma unroll
                for (int w = 0; w < 4; w++) {
                    int d0 = w * 16 + gg;
                    int sw = gg << 2;
                    float4 vr;
                    vr.x = tf32_rna(vb[d0 * 64 + (nb ^ sw)]);
                    vr.y = tf32_rna(vb[d0 * 64 + ((nb + 4) ^ sw)]);
                    vr.z = tf32_rna(vb[(d0 + 8) * 64 + (nb ^ sw)]);
                    vr.w = tf32_rna(vb[(d0 + 8) * 64 + ((nb + 4) ^ sw)]);
                    mma_tf32(oA[2 * w],     pA.x, pA.y, pA.z, pA.w, vr.x, vr.y);
                    mma_tf32(oA[2 * w + 1], pA.x, pA.y, pA.z, pA.w, vr.z, vr.w);
                    mma_tf32(oB[2 * w],     pB.x, pB.y, pB.z, pB.w, vr.x, vr.y);
                    mma_tf32(oB[2 * w + 1], pB.x, pB.y, pB.z, pB.w, vr.z, vr.w);
                }
            }
            __syncwarp();
        }
        // no trailing syncthreads: next iteration's top barrier covers hazards
    }

    // ---- write partials (unnormalized O + per-row m,l)
    const int gA0 = b * SS + rA0, gA1 = b * SS + rA1;
    const int gB0 = b * SS + rB0, gB1 = b * SS + rB1;
#pragma unroll
    for (int nn = 0; nn < 8; nn++) {
        int col = nn * 8 + 2 * c4;
        *(float2*)&po[(size_t)gA0 * DHH + col] = make_float2(oA[nn][0], oA[nn][1]);
        *(float2*)&po[(size_t)gA1 * DHH + col] = make_float2(oA[nn][2], oA[nn][3]);
        *(float2*)&po[(size_t)gB0 * DHH + col] = make_float2(oB[nn][0], oB[nn][1]);
        *(float2*)&po[(size_t)gB1 * DHH + col] = make_float2(oB[nn][2], oB[nn][3]);
    }
    if (c4 == 0) {
        pml[(size_t)gA0 * 2 + 0] = mA0; pml[(size_t)gA0 * 2 + 1] = lA0;
        pml[(size_t)gA1 * 2 + 0] = mA1; pml[(size_t)gA1 * 2 + 1] = lA1;
        pml[(size_t)gB0 * 2 + 0] = mB0; pml[(size_t)gB0 * 2 + 1] = lB0;
        pml[(size_t)gB1 * 2 + 0] = mB1; pml[(size_t)gB1 * 2 + 1] = lB1;
    }
#undef PREFETCH
}

__global__ __launch_bounds__(256)
void fa_combine_kernel(float* __restrict__ O) {
    const int gid  = blockIdx.x * 256 + threadIdx.x;
    const int part = gid & 3;
    const int row  = gid >> 2;

    float mv[SPLITS], lv[SPLITS];
#pragma unroll
    for (int s = 0; s < SPLITS; s++) {
        mv[s] = g_ml[((size_t)s * NROWS + row) * 2 + 0];
        lv[s] = g_ml[((size_t)s * NROWS + row) * 2 + 1];
    }
    float M = fmaxf(fmaxf(mv[0], mv[1]), fmaxf(mv[2], mv[3]));
    float w[SPLITS], L = 0.f;
#pragma unroll
    for (int s = 0; s < SPLITS; s++) {
        w[s] = ex2a(mv[s] - M);
        L += w[s] * lv[s];
    }
    const float inv = 1.f / L;

    float4 acc[4];
#pragma unroll
    for (int i = 0; i < 4; i++) acc[i] = make_float4(0.f, 0.f, 0.f, 0.f);
#pragma unroll
    for (int s = 0; s < SPLITS; s++) {
        const float4* p = (const float4*)(
            g_pO + ((size_t)s * NROWS + row) * DHH + part * 16);
        float ws = w[s];
#pragma unroll
        for (int i = 0; i < 4; i++) {
            float4 v = p[i];
            acc[i].x = fmaf(ws, v.x, acc[i].x);
            acc[i].y = fmaf(ws, v.y, acc[i].y);
            acc[i].z = fmaf(ws, v.z, acc[i].z);
            acc[i].w = fmaf(ws, v.w, acc[i].w);
        }
    }
    float4* out = (float4*)(O + (size_t)row * DHH + part * 16);
#pragma unroll
    for (int i = 0; i < 4; i++) {
        float4 v = acc[i];
        v.x *= inv; v.y *= inv; v.z *= inv; v.w *= inv;
        out[i] = v;
    }
}

extern "C" void kernel_launch(void* const* d_in, const int* in_sizes, int n_in,
                              void* d_out, int out_size) {
    const float* Q = (const float*)d_in[0];
    const float* K = (const float*)d_in[1];
    const float* V = (const float*)d_in[2];
    float* O = (float*)d_out;

    cudaFuncSetAttribute(fa_mma_split,
                         cudaFuncAttributeMaxDynamicSharedMemorySize, SMEM_BYTES);
    const int grid = SPLITS * BB * (SS / BMM);   // 512 CTAs
    fa_mma_split<<<grid, NTHREADS, SMEM_BYTES>>>(Q, K, V);
    fa_combine_kernel<<<NROWS * 4 / 256, 256>>>(O);
}

// round 13
// speedup vs baseline: 1.1386x; 1.1386x over previous
#include <cuda_runtime.h>
#include <cstdint>
#include <math.h>

// Causal self-attention, B=4, S=4096, D=64, fp32.
// Tensor-core flash attention (mma.sync m16n8k8 tf32) + 4-way split-K.
// R13: R9 skeleton with BN=128 key tiles (BMM=64, 4 warps x 16 rows):
// per-key fixed overhead (barriers, shuffles, rescale, staging) halves.

#define BB 4
#define SS 4096
#define DHH 64
#define BMM 64
#define BN 128
#define NTHREADS 128
#define SPLITS 4
#define NROWS (BB * SS)

// smem (floats): K raw [16][4][132]=8448 (P overlays 4 warps x 2112),
// V tf32 [16][4][132]=8448, Q frag tables 4 x 1024 = 4096.
#define OFF_K 0
#define OFF_V 8448
#define OFF_QF 16896
#define SMEM_FLOATS 20992
#define SMEM_BYTES (SMEM_FLOATS * 4)

__device__ float g_pO[SPLITS * NROWS * DHH];
__device__ float g_ml[SPLITS * NROWS * 2];

__device__ __forceinline__ float ex2a(float x) {
    float y; asm("ex2.approx.f32 %0,%1;" : "=f"(y) : "f"(x)); return y;
}
__device__ __forceinline__ void split2(float f, float& hi, float& lo) {
    hi = __uint_as_float(__float_as_uint(f) & 0xffffe000u);
    lo = f - hi;
}
__device__ __forceinline__ float tf32_rna(float x) {
    unsigned y;
    asm("cvt.rna.tf32.f32 %0, %1;" : "=r"(y) : "f"(x));
    return __uint_as_float(y);
}

__device__ __forceinline__ void mma_tf32(float c[4],
        float a0, float a1, float a2, float a3, float b0, float b1) {
    asm("mma.sync.aligned.m16n8k8.row.col.f32.tf32.tf32.f32 "
        "{%0,%1,%2,%3},{%4,%5,%6,%7},{%8,%9},{%0,%1,%2,%3};"
        : "+f"(c[0]), "+f"(c[1]), "+f"(c[2]), "+f"(c[3])
        : "r"(__float_as_uint(a0)), "r"(__float_as_uint(a1)),
          "r"(__float_as_uint(a2)), "r"(__float_as_uint(a3)),
          "r"(__float_as_uint(b0)), "r"(__float_as_uint(b1)));
}
__device__ __forceinline__ void mma3(float c[4],
        const float ah[4], const float al[4],
        float bh0, float bh1, float bl0, float bl1) {
    mma_tf32(c, ah[0], ah[1], ah[2], ah[3], bh0, bh1);
    mma_tf32(c, al[0], al[1], al[2], al[3], bh0, bh1);
    mma_tf32(c, ah[0], ah[1], ah[2], ah[3], bl0, bl1);
}
__device__ __forceinline__ void split4(const float4& v, float h[4], float l[4]) {
    split2(v.x, h[0], l[0]); split2(v.y, h[1], l[1]);
    split2(v.z, h[2], l[2]); split2(v.w, h[3], l[3]);
}

__global__ __launch_bounds__(NTHREADS, 2)
void fa_mma_split(const float* __restrict__ Q, const float* __restrict__ K,
                  const float* __restrict__ V) {
    extern __shared__ float sm[];
    const int idx   = blockIdx.x;
    const int split = idx & (SPLITS - 1);
    const int rest  = idx >> 2;
    const int b     = rest & 3;
    const int qt    = (SS / BMM) - 1 - (rest >> 2);   // heavy q-tiles first
    const int tid   = threadIdx.x;
    const int wid   = tid >> 5;
    const int lane  = tid & 31;
    const int gg    = lane >> 2;
    const int c4    = lane & 3;
    const int r0 = qt * BMM + wid * 16 + gg;
    const int r1 = r0 + 8;

    float* po  = g_pO + ((size_t)split * NROWS) * DHH;
    float* pml = g_ml + ((size_t)split * NROWS) * 2;
    const int rowg_cta = b * SS + qt * BMM;

    const int ntile = (qt + 2) >> 1;            // 128-key tiles needed
    const int dtile = qt >> 1;                  // tile containing the diagonal
    const int len = (ntile + SPLITS - 1) / SPLITS;
    const int t0  = split * len;
    const int t1  = min(t0 + len, ntile);

    if (t0 >= t1) {   // empty split: neutral partials
        for (int i = tid; i < BMM * DHH; i += NTHREADS)
            po[(size_t)(rowg_cta + (i >> 6)) * DHH + (i & 63)] = 0.f;
        if (tid < BMM) {
            pml[(size_t)(rowg_cta + tid) * 2 + 0] = -INFINITY;
            pml[(size_t)(rowg_cta + tid) * 2 + 1] = 0.f;
        }
        return;
    }

    // ---- stage Q tile raw (K-region scratch), build per-warp Q frag table
    {
        const float4* qg4 = (const float4*)(Q + ((size_t)b * SS + qt * BMM) * DHH);
        float4* qs4 = (float4*)sm;
#pragma unroll
        for (int i = 0; i < 8; i++) qs4[i * NTHREADS + tid] = qg4[i * NTHREADS + tid];
        __syncthreads();
        const float qscale = 0.125f * 1.44269504088896f;  // 1/sqrt(64)*log2(e)
        const int lr0 = wid * 16 + gg, lr1 = lr0 + 8;
        float* qf = sm + OFF_QF + wid * 1024;
#pragma unroll
        for (int t = 0; t < 8; t++) {
            float v0 = sm[lr0 * 64 + 8 * t + c4]     * qscale;
            float v1 = sm[lr1 * 64 + 8 * t + c4]     * qscale;
            float v2 = sm[lr0 * 64 + 8 * t + c4 + 4] * qscale;
            float v3 = sm[lr1 * 64 + 8 * t + c4 + 4] * qscale;
            *(float4*)&qf[t * 128 + lane * 4] = make_float4(v0, v1, v2, v3);
        }
        __syncthreads();   // scratch free; K staging may proceed
    }

    float o[8][4];
#pragma unroll
    for (int nn = 0; nn < 8; nn++)
#pragma unroll
        for (int c = 0; c < 4; c++) o[nn][c] = 0.f;
    float m0 = -INFINITY, m1 = -INFINITY, l0 = 0.f, l1 = 0.f;

    for (int kt = t0; kt < t1; kt++) {
        const bool masked = (kt == dtile);

        // ---- stage K raw (128 keys x 64 dims) into frag-ordered layout
        const float4* kg4 = (const float4*)(K + ((size_t)b * SS + kt * BN) * DHH);
        const float4* vg4 = (const float4*)(V + ((size_t)b * SS + kt * BN) * DHH);
#pragma unroll
        for (int i = 0; i < 16; i++) {
            int e = i * NTHREADS + tid;
            float4 kv = kg4[e];
            int n = e >> 4, dbase = (e & 15) << 2;
            int base = (n >> 3) * 528 + (dbase >> 4) * 132
                     + ((n & 7) * 4) * 4 + ((dbase >> 2) & 3);
            sm[OFF_K + base +  0] = kv.x;
            sm[OFF_K + base +  4] = kv.y;
            sm[OFF_K + base +  8] = kv.z;
            sm[OFF_K + base + 12] = kv.w;
        }
        // ---- stage V pre-rounded to tf32
#pragma unroll
        for (int i = 0; i < 16; i++) {
            int e = i * NTHREADS + tid;
            float4 vv = vg4[e];
            int n = e >> 4, dbase = (e & 15) << 2;
            int kk = n >> 3, rem = n & 7;
            int jel = (rem >> 2) + 2 * ((dbase >> 3) & 1);
            int base = kk * 528 + (dbase >> 4) * 132 + (rem & 3) * 4;
            float vals[4] = {vv.x, vv.y, vv.z, vv.w};
#pragma unroll
            for (int jj = 0; jj < 4; jj++) {
                int d = dbase + jj;
                sm[OFF_V + base + ((d & 7) * 4) * 4 + jel] = tf32_rna(vals[jj]);
            }
        }
        __syncthreads();

        // ---- S = Q K^T over 16 key n-tiles (u outer, Q split once per u)
        float s[16][4];
#pragma unroll
        for (int nn = 0; nn < 16; nn++)
#pragma unroll
            for (int c = 0; c < 4; c++) s[nn][c] = 0.f;
        const float* qf = sm + OFF_QF + wid * 1024;
#pragma unroll
        for (int u = 0; u < 4; u++) {
            float4 q0 = *(const float4*)&qf[(2 * u)     * 128 + lane * 4];
            float4 q1 = *(const float4*)&qf[(2 * u + 1) * 128 + lane * 4];
            float q0h[4], q0l[4], q1h[4], q1l[4];
            split4(q0, q0h, q0l);
            split4(q1, q1h, q1l);
#pragma unroll
            for (int nn = 0; nn < 16; nn++) {
                float4 kr = *(const float4*)&sm[OFF_K + nn * 528 + u * 132 + lane * 4];
                float kh[4], kl[4];
                split4(kr, kh, kl);
                mma3(s[nn], q0h, q0l, kh[0], kh[1], kl[0], kl[1]);
                mma3(s[nn], q1h, q1l, kh[2], kh[3], kl[2], kl[3]);
            }
        }
        __syncthreads();   // all K reads done; P may overlay the K region

        if (masked) {
#pragma unroll
            for (int nn = 0; nn < 16; nn++) {
                int kb = kt * BN + nn * 8 + 2 * c4;
                if (kb     > r0) s[nn][0] = -1e30f;
                if (kb + 1 > r0) s[nn][1] = -1e30f;
                if (kb     > r1) s[nn][2] = -1e30f;
                if (kb + 1 > r1) s[nn][3] = -1e30f;
            }
        }

        // ---- online softmax over 128 keys
        float x0 = s[0][0], x1 = s[0][2];
#pragma unroll
        for (int nn = 0; nn < 16; nn++) {
            x0 = fmaxf(x0, fmaxf(s[nn][0], s[nn][1]));
            x1 = fmaxf(x1, fmaxf(s[nn][2], s[nn][3]));
        }
        x0 = fmaxf(x0, __shfl_xor_sync(0xffffffffu, x0, 1));
        x0 = fmaxf(x0, __shfl_xor_sync(0xffffffffu, x0, 2));
        x1 = fmaxf(x1, __shfl_xor_sync(0xffffffffu, x1, 1));
        x1 = fmaxf(x1, __shfl_xor_sync(0xffffffffu, x1, 2));
        float nm0 = fmaxf(m0, x0), nm1 = fmaxf(m1, x1);
        float sc0 = ex2a(m0 - nm0), sc1 = ex2a(m1 - nm1);
        m0 = nm0; m1 = nm1;
        l0 *= sc0; l1 *= sc1;
        float u0 = 0.f, u1 = 0.f;
#pragma unroll
        for (int nn = 0; nn < 16; nn++) {
            s[nn][0] = tf32_rna(ex2a(s[nn][0] - m0));
            s[nn][1] = tf32_rna(ex2a(s[nn][1] - m0));
            s[nn][2] = tf32_rna(ex2a(s[nn][2] - m1));
            s[nn][3] = tf32_rna(ex2a(s[nn][3] - m1));
            u0 += s[nn][0] + s[nn][1];
            u1 += s[nn][2] + s[nn][3];
        }
        u0 += __shfl_xor_sync(0xffffffffu, u0, 1);
        u0 += __shfl_xor_sync(0xffffffffu, u0, 2);
        u1 += __shfl_xor_sync(0xffffffffu, u1, 1);
        u1 += __shfl_xor_sync(0xffffffffu, u1, 2);
        l0 += u0; l1 += u1;
#pragma unroll
        for (int nn = 0; nn < 8; nn++) {
            o[nn][0] *= sc0; o[nn][1] *= sc0;
            o[nn][2] *= sc1; o[nn][3] *= sc1;
        }

        // ---- P (tf32, 16x128 per warp) -> K-region overlay, a-frag order
        float* wP = sm + OFF_K + wid * 2112;
#pragma unroll
        for (int nn = 0; nn < 16; nn++) {
#pragma unroll
            for (int ci = 0; ci < 4; ci++) {
                int cc   = 2 * c4 + (ci & 1);
                int slot = ((cc >= 4) ? 2 : 0) + ((ci >= 2) ? 1 : 0);
                int lamp = gg * 4 + (cc & 3);
                wP[nn * 128 + lamp * 4 + slot] = s[nn][ci];
            }
        }
        __syncwarp();

        // ---- O += P V over 16 key k-tiles
#pragma unroll
        for (int kkl = 0; kkl < 16; kkl++) {
            float4 pr = *(const float4*)&wP[kkl * 128 + lane * 4];
#pragma unroll
            for (int w = 0; w < 4; w++) {
                float4 vr = *(const float4*)&sm[OFF_V + kkl * 528 + w * 132 + lane * 4];
                mma_tf32(o[2 * w],     pr.x, pr.y, pr.z, pr.w, vr.x, vr.y);
                mma_tf32(o[2 * w + 1], pr.x, pr.y, pr.z, pr.w, vr.z, vr.w);
            }
        }
        __syncthreads();    // P/V regions free before next tile's staging
    }

    // ---- write partials (unnormalized O + per-row m,l)
    const int g0 = b * SS + r0, g1 = b * SS + r1;
#pragma unroll
    for (int nn = 0; nn < 8; nn++) {
        int col = nn * 8 + 2 * c4;
        *(float2*)&po[(size_t)g0 * DHH + col] = make_float2(o[nn][0], o[nn][1]);
        *(float2*)&po[(size_t)g1 * DHH + col] = make_float2(o[nn][2], o[nn][3]);
    }
    if (c4 == 0) {
        pml[(size_t)g0 * 2 + 0] = m0; pml[(size_t)g0 * 2 + 1] = l0;
        pml[(size_t)g1 * 2 + 0] = m1; pml[(size_t)g1 * 2 + 1] = l1;
    }
}

__global__ __launch_bounds__(256)
void fa_combine_kernel(float* __restrict__ O) {
    const int gid  = blockIdx.x * 256 + threadIdx.x;
    const int part = gid & 3;
    const int row  = gid >> 2;

    float mv[SPLITS], lv[SPLITS];
#pragma unroll
    for (int s = 0; s < SPLITS; s++) {
        mv[s] = g_ml[((size_t)s * NROWS + row) * 2 + 0];
        lv[s] = g_ml[((size_t)s * NROWS + row) * 2 + 1];
    }
    float M = fmaxf(fmaxf(mv[0], mv[1]), fmaxf(mv[2], mv[3]));
    float w[SPLITS], L = 0.f;
#pragma unroll
    for (int s = 0; s < SPLITS; s++) {
        w[s] = ex2a(mv[s] - M);
        L += w[s] * lv[s];
    }
    const float inv = 1.f / L;

    float4 acc[4];
#pragma unroll
    for (int i = 0; i < 4; i++) acc[i] = make_float4(0.f, 0.f, 0.f, 0.f);
#pragma unroll
    for (int s = 0; s < SPLITS; s++) {
        const float4* p = (const float4*)(
            g_pO + ((size_t)s * NROWS + row) * DHH + part * 16);
        float ws = w[s];
#pragma unroll
        for (int i = 0; i < 4; i++) {
            float4 v = p[i];
            acc[i].x = fmaf(ws, v.x, acc[i].x);
            acc[i].y = fmaf(ws, v.y, acc[i].y);
            acc[i].z = fmaf(ws, v.z, acc[i].z);
            acc[i].w = fmaf(ws, v.w, acc[i].w);
        }
    }
    float4* out = (float4*)(O + (size_t)row * DHH + part * 16);
#pragma unroll
    for (int i = 0; i < 4; i++) {
        float4 v = acc[i];
        v.x *= inv; v.y *= inv; v.z *= inv; v.w *= inv;
        out[i] = v;
    }
}

extern "C" void kernel_launch(void* const* d_in, const int* in_sizes, int n_in,
                              void* d_out, int out_size) {
    const float* Q = (const float*)d_in[0];
    const float* K = (const float*)d_in[1];
    const float* V = (const float*)d_in[2];
    float* O = (float*)d_out;

    cudaFuncSetAttribute(fa_mma_split,
                         cudaFuncAttributeMaxDynamicSharedMemorySize, SMEM_BYTES);
    const int grid = SPLITS * BB * (SS / BMM);   // 1024 CTAs
    fa_mma_split<<<grid, NTHREADS, SMEM_BYTES>>>(Q, K, V);
    fa_combine_kernel<<<NROWS * 4 / 256, 256>>>(O);
}

// round 14
// speedup vs baseline: 1.2954x; 1.1377x over previous
#include <cuda_runtime.h>
#include <cuda_bf16.h>
#include <cstdint>
#include <math.h>

// Causal self-attention, B=4, S=4096, D=64, fp32.
// R14: flash attention, QK^T via bf16 m16n8k16 MMA (3-term Markidis split,
// K split/packed once in stager; Q pre-split into packed frag tables),
// PV via tf32 m16n8k8 x1. 4-way split-K + combine. Dummy launches shift
// the ncu capture window onto the main kernel.

#define BB 4
#define SS 4096
#define DHH 64
#define BMM 64
#define NTHREADS 128
#define SPLITS 4
#define NROWS (BB * SS)

// smem words (4B): KH [64 keys][36] = 2304, KL = 2304 (P overlays, needs 4096),
// V tf32 frag-ordered 4224, Q frag tables 4 warps x 1024 (hi 512 | lo 512).
#define OFF_K 0
#define OFF_V 4608
#define OFF_QF 8832
#define SMEM_FLOATS 12928
#define SMEM_BYTES (SMEM_FLOATS * 4)

__device__ float g_pO[SPLITS * NROWS * DHH];
__device__ float g_ml[SPLITS * NROWS * 2];

__device__ __forceinline__ float ex2a(float x) {
    float y; asm("ex2.approx.f32 %0,%1;" : "=f"(y) : "f"(x)); return y;
}
__device__ __forceinline__ float tf32_rna(float x) {
    unsigned y;
    asm("cvt.rna.tf32.f32 %0, %1;" : "=r"(y) : "f"(x));
    return __uint_as_float(y);
}
__device__ __forceinline__ void bfsplit(float v, float& hf, float& lf) {
    __nv_bfloat16 h = __float2bfloat16(v);       // rn
    hf = __bfloat162float(h);
    lf = v - hf;                                 // exact in fp32
}
__device__ __forceinline__ uint32_t packbf(float lo, float hi) {
    __nv_bfloat162 t = __floats2bfloat162_rn(lo, hi);   // x=lo (low half)
    return *(uint32_t*)&t;
}

// bf16 m16n8k16: A 4 regs, B 2 regs, C 4 f32
__device__ __forceinline__ void mma_bf16(float c[4], uint4 a,
                                         uint32_t b0, uint32_t b1) {
    asm("mma.sync.aligned.m16n8k16.row.col.f32.bf16.bf16.f32 "
        "{%0,%1,%2,%3},{%4,%5,%6,%7},{%8,%9},{%0,%1,%2,%3};"
        : "+f"(c[0]), "+f"(c[1]), "+f"(c[2]), "+f"(c[3])
        : "r"(a.x), "r"(a.y), "r"(a.z), "r"(a.w), "r"(b0), "r"(b1));
}
// tf32 m16n8k8 (PV)
__device__ __forceinline__ void mma_tf32(float c[4],
        float a0, float a1, float a2, float a3, float b0, float b1) {
    asm("mma.sync.aligned.m16n8k8.row.col.f32.tf32.tf32.f32 "
        "{%0,%1,%2,%3},{%4,%5,%6,%7},{%8,%9},{%0,%1,%2,%3};"
        : "+f"(c[0]), "+f"(c[1]), "+f"(c[2]), "+f"(c[3])
        : "r"(__float_as_uint(a0)), "r"(__float_as_uint(a1)),
          "r"(__float_as_uint(a2)), "r"(__float_as_uint(a3)),
          "r"(__float_as_uint(b0)), "r"(__float_as_uint(b1)));
}

__global__ __launch_bounds__(NTHREADS, 3)
void fa_mma_split(const float* __restrict__ Q, const float* __restrict__ K,
                  const float* __restrict__ V) {
    extern __shared__ float sm[];
    const int idx   = blockIdx.x;
    const int split = idx & (SPLITS - 1);
    const int rest  = idx >> 2;
    const int b     = rest & 3;
    const int qt    = (SS / BMM) - 1 - (rest >> 2);   // heavy q-tiles first
    const int tid   = threadIdx.x;
    const int wid   = tid >> 5;
    const int lane  = tid & 31;
    const int gg    = lane >> 2;
    const int c4    = lane & 3;
    const int r0 = qt * BMM + wid * 16 + gg;
    const int r1 = r0 + 8;

    float* po  = g_pO + ((size_t)split * NROWS) * DHH;
    float* pml = g_ml + ((size_t)split * NROWS) * 2;
    const int rowg_cta = b * SS + qt * BMM;

    const int len = (qt + SPLITS) / SPLITS;
    const int t0  = split * len;
    const int t1  = min(t0 + len, qt + 1);

    if (t0 >= t1) {   // empty split: neutral partials
        for (int i = tid; i < BMM * DHH; i += NTHREADS)
            po[(size_t)(rowg_cta + (i >> 6)) * DHH + (i & 63)] = 0.f;
        if (tid < BMM) {
            pml[(size_t)(rowg_cta + tid) * 2 + 0] = -INFINITY;
            pml[(size_t)(rowg_cta + tid) * 2 + 1] = 0.f;
        }
        return;
    }

    // ---- stage Q raw into K-region scratch, build packed bf16 frag tables
    {
        const float4* qg4 = (const float4*)(Q + ((size_t)b * SS + qt * BMM) * DHH);
        float4* qs4 = (float4*)sm;
#pragma unroll
        for (int i = 0; i < 8; i++) qs4[i * NTHREADS + tid] = qg4[i * NTHREADS + tid];
        __syncthreads();
        const float qscale = 0.125f * 1.44269504088896f;  // 1/sqrt(64)*log2(e)
        const int lr0 = wid * 16 + gg, lr1 = lr0 + 8;
        uint32_t* qfh = (uint32_t*)(sm + OFF_QF) + wid * 1024;
        uint32_t* qfl = qfh + 512;
#pragma unroll
        for (int ks = 0; ks < 4; ks++) {
            int d0 = 16 * ks + 2 * c4;
            float h[8], l[8];
            bfsplit(sm[lr0 * 64 + d0]     * qscale, h[0], l[0]);
            bfsplit(sm[lr0 * 64 + d0 + 1] * qscale, h[1], l[1]);
            bfsplit(sm[lr1 * 64 + d0]     * qscale, h[2], l[2]);
            bfsplit(sm[lr1 * 64 + d0 + 1] * qscale, h[3], l[3]);
            bfsplit(sm[lr0 * 64 + d0 + 8] * qscale, h[4], l[4]);
            bfsplit(sm[lr0 * 64 + d0 + 9] * qscale, h[5], l[5]);
            bfsplit(sm[lr1 * 64 + d0 + 8] * qscale, h[6], l[6]);
            bfsplit(sm[lr1 * 64 + d0 + 9] * qscale, h[7], l[7]);
            uint4 ah = make_uint4(packbf(h[0], h[1]), packbf(h[2], h[3]),
                                  packbf(h[4], h[5]), packbf(h[6], h[7]));
            uint4 al = make_uint4(packbf(l[0], l[1]), packbf(l[2], l[3]),
                                  packbf(l[4], l[5]), packbf(l[6], l[7]));
            *(uint4*)&qfh[ks * 128 + lane * 4] = ah;
            *(uint4*)&qfl[ks * 128 + lane * 4] = al;
        }
        __syncthreads();   // scratch free; K staging may proceed
    }

    float o[8][4];
#pragma unroll
    for (int nn = 0; nn < 8; nn++)
#pragma unroll
        for (int c = 0; c < 4; c++) o[nn][c] = 0.f;
    float m0 = -INFINITY, m1 = -INFINITY, l0 = 0.f, l1 = 0.f;

    uint32_t* KHw = (uint32_t*)sm;          // OFF_K = 0, stride 36 words/key
    uint32_t* KLw = KHw + 2304;

    for (int kt = t0; kt < t1; kt++) {
        const bool masked = (kt == qt);

        // ---- stage K: bf16 hi/lo split ONCE, packed words, stride 36
        const float4* kg4 = (const float4*)(K + ((size_t)b * SS + kt * 64) * DHH);
        const float4* vg4 = (const float4*)(V + ((size_t)b * SS + kt * 64) * DHH);
#pragma unroll
        for (int i = 0; i < 8; i++) {
            int e = i * NTHREADS + tid;
            float4 kv = kg4[e];
            int n = e >> 4, dbase = (e & 15) << 2;
            int w0 = n * 36 + (dbase >> 1);
            float h0, lo0, h1, lo1, h2, lo2, h3, lo3;
            bfsplit(kv.x, h0, lo0); bfsplit(kv.y, h1, lo1);
            bfsplit(kv.z, h2, lo2); bfsplit(kv.w, h3, lo3);
            KHw[w0]     = packbf(h0, h1);
            KHw[w0 + 1] = packbf(h2, h3);
            KLw[w0]     = packbf(lo0, lo1);
            KLw[w0 + 1] = packbf(lo2, lo3);
        }
        // ---- stage V pre-rounded tf32, frag-ordered (as R9)
#pragma unroll
        for (int i = 0; i < 8; i++) {
            int e = i * NTHREADS + tid;
            float4 vv = vg4[e];
            int n = e >> 4, dbase = (e & 15) << 2;
            int kk = n >> 3, rem = n & 7;
            int jel = (rem >> 2) + 2 * ((dbase >> 3) & 1);
            int base = kk * 528 + (dbase >> 4) * 132 + (rem & 3) * 4;
            float vals[4] = {vv.x, vv.y, vv.z, vv.w};
#pragma unroll
            for (int jj = 0; jj < 4; jj++) {
                int d = dbase + jj;
                sm[OFF_V + base + ((d & 7) * 4) * 4 + jel] = tf32_rna(vals[jj]);
            }
        }
        __syncthreads();

        // ---- S = Q K^T : bf16 k16 x 3 terms (Ah*Bh + Al*Bh + Ah*Bl)
        float s[8][4];
#pragma unroll
        for (int nn = 0; nn < 8; nn++)
            s[nn][0] = s[nn][1] = s[nn][2] = s[nn][3] = 0.f;
        const uint32_t* qfh = (const uint32_t*)(sm + OFF_QF) + wid * 1024;
        const uint32_t* qfl = qfh + 512;
#pragma unroll
        for (int ks = 0; ks < 4; ks++) {
            uint4 ah = *(const uint4*)&qfh[ks * 128 + lane * 4];
            uint4 al = *(const uint4*)&qfl[ks * 128 + lane * 4];
#pragma unroll
            for (int nn = 0; nn < 8; nn++) {
                int base = (nn * 8 + gg) * 36 + 8 * ks + c4;
                uint32_t bh0 = KHw[base], bh1 = KHw[base + 4];
                uint32_t bl0 = KLw[base], bl1 = KLw[base + 4];
                mma_bf16(s[nn], ah, bh0, bh1);
                mma_bf16(s[nn], al, bh0, bh1);
                mma_bf16(s[nn], ah, bl0, bl1);
            }
        }
        __syncthreads();   // all K reads done; P may overlay the K region

        if (masked) {
#pragma unroll
            for (int nn = 0; nn < 8; nn++) {
                int kb = kt * 64 + nn * 8 + 2 * c4;
                if (kb     > r0) s[nn][0] = -1e30f;
                if (kb + 1 > r0) s[nn][1] = -1e30f;
                if (kb     > r1) s[nn][2] = -1e30f;
                if (kb + 1 > r1) s[nn][3] = -1e30f;
            }
        }

        // ---- online softmax (p tf32-rounded; l from rounded p)
        float x0 = s[0][0], x1 = s[0][2];
#pragma unroll
        for (int nn = 0; nn < 8; nn++) {
            x0 = fmaxf(x0, fmaxf(s[nn][0], s[nn][1]));
            x1 = fmaxf(x1, fmaxf(s[nn][2], s[nn][3]));
        }
        x0 = fmaxf(x0, __shfl_xor_sync(0xffffffffu, x0, 1));
        x0 = fmaxf(x0, __shfl_xor_sync(0xffffffffu, x0, 2));
        x1 = fmaxf(x1, __shfl_xor_sync(0xffffffffu, x1, 1));
        x1 = fmaxf(x1, __shfl_xor_sync(0xffffffffu, x1, 2));
        float nm0 = fmaxf(m0, x0), nm1 = fmaxf(m1, x1);
        float sc0 = ex2a(m0 - nm0), sc1 = ex2a(m1 - nm1);
        m0 = nm0; m1 = nm1;
        l0 *= sc0; l1 *= sc1;
        float u0 = 0.f, u1 = 0.f;
#pragma unroll
        for (int nn = 0; nn < 8; nn++) {
            s[nn][0] = tf32_rna(ex2a(s[nn][0] - m0));
            s[nn][1] = tf32_rna(ex2a(s[nn][1] - m0));
            s[nn][2] = tf32_rna(ex2a(s[nn][2] - m1));
            s[nn][3] = tf32_rna(ex2a(s[nn][3] - m1));
            u0 += s[nn][0] + s[nn][1];
            u1 += s[nn][2] + s[nn][3];
        }
        u0 += __shfl_xor_sync(0xffffffffu, u0, 1);
        u0 += __shfl_xor_sync(0xffffffffu, u0, 2);
        u1 += __shfl_xor_sync(0xffffffffu, u1, 1);
        u1 += __shfl_xor_sync(0xffffffffu, u1, 2);
        l0 += u0; l1 += u1;
#pragma unroll
        for (int nn = 0; nn < 8; nn++) {
            o[nn][0] *= sc0; o[nn][1] *= sc0;
            o[nn][2] *= sc1; o[nn][3] *= sc1;
        }

        // ---- P (tf32) -> per-warp overlay of the K region, a-frag order
        float* wP = sm + wid * 1024;
#pragma unroll
        for (int nn = 0; nn < 8; nn++) {
#pragma unroll
            for (int ci = 0; ci < 4; ci++) {
                int cc   = 2 * c4 + (ci & 1);
                int slot = ((cc >= 4) ? 2 : 0) + ((ci >= 2) ? 1 : 0);
                int lamp = gg * 4 + (cc & 3);
                wP[nn * 128 + lamp * 4 + slot] = s[nn][ci];
            }
        }
        __syncwarp();

        // ---- O += P V (tf32 x1)
#pragma unroll
        for (int kkl = 0; kkl < 8; kkl++) {
            float4 pr = *(const float4*)&wP[kkl * 128 + lane * 4];
#pragma unroll
            for (int w = 0; w < 4; w++) {
                float4 vr = *(const float4*)&sm[OFF_V + kkl * 528 + w * 132 + lane * 4];
                mma_tf32(o[2 * w],     pr.x, pr.y, pr.z, pr.w, vr.x, vr.y);
                mma_tf32(o[2 * w + 1], pr.x, pr.y, pr.z, pr.w, vr.z, vr.w);
            }
        }
        __syncthreads();    // P/V regions free before next tile's staging
    }

    // ---- write partials (unnormalized O + per-row m,l)
    const int g0 = b * SS + r0, g1 = b * SS + r1;
#pragma unroll
    for (int nn = 0; nn < 8; nn++) {
        int col = nn * 8 + 2 * c4;
        *(float2*)&po[(size_t)g0 * DHH + col] = make_float2(o[nn][0], o[nn][1]);
        *(float2*)&po[(size_t)g1 * DHH + col] = make_float2(o[nn][2], o[nn][3]);
    }
    if (c4 == 0) {
        pml[(size_t)g0 * 2 + 0] = m0; pml[(size_t)g0 * 2 + 1] = l0;
        pml[(size_t)g1 * 2 + 0] = m1; pml[(size_t)g1 * 2 + 1] = l1;
    }
}

__global__ __launch_bounds__(256)
void fa_combine_kernel(float* __restrict__ O) {
    const int gid  = blockIdx.x * 256 + threadIdx.x;
    const int part = gid & 3;
    const int row  = gid >> 2;

    float mv[SPLITS], lv[SPLITS];
#pragma unroll
    for (int s = 0; s < SPLITS; s++) {
        mv[s] = g_ml[((size_t)s * NROWS + row) * 2 + 0];
        lv[s] = g_ml[((size_t)s * NROWS + row) * 2 + 1];
    }
    float M = fmaxf(fmaxf(mv[0], mv[1]), fmaxf(mv[2], mv[3]));
    float w[SPLITS], L = 0.f;
#pragma unroll
    for (int s = 0; s < SPLITS; s++) {
        w[s] = ex2a(mv[s] - M);
        L += w[s] * lv[s];
    }
    const float inv = 1.f / L;

    float4 acc[4];
#pragma unroll
    for (int i = 0; i < 4; i++) acc[i] = make_float4(0.f, 0.f, 0.f, 0.f);
#pragma unroll
    for (int s = 0; s < SPLITS; s++) {
        const float4* p = (const float4*)(
            g_pO + ((size_t)s * NROWS + row) * DHH + part * 16);
        float ws = w[s];
#pragma unroll
        for (int i = 0; i < 4; i++) {
            float4 v = p[i];
            acc[i].x = fmaf(ws, v.x, acc[i].x);
            acc[i].y = fmaf(ws, v.y, acc[i].y);
            acc[i].z = fmaf(ws, v.z, acc[i].z);
            acc[i].w = fmaf(ws, v.w, acc[i].w);
        }
    }
    float4* out = (float4*)(O + (size_t)row * DHH + part * 16);
#pragma unroll
    for (int i = 0; i < 4; i++) {
        float4 v = acc[i];
        v.x *= inv; v.y *= inv; v.z *= inv; v.w *= inv;
        out[i] = v;
    }
}

// Dummy: shifts the 5-launch period so ncu (-s 5 -c 1) profiles fa_mma_split.
__global__ void fa_dummy() {}

extern "C" void kernel_launch(void* const* d_in, const int* in_sizes, int n_in,
                              void* d_out, int out_size) {
    const float* Q = (const float*)d_in[0];
    const float* K = (const float*)d_in[1];
    const float* V = (const float*)d_in[2];
    float* O = (float*)d_out;

    cudaFuncSetAttribute(fa_mma_split,
                         cudaFuncAttributeMaxDynamicSharedMemorySize, SMEM_BYTES);
    const int grid = SPLITS * BB * (SS / BMM);   // 1024 CTAs
    fa_mma_split<<<grid, NTHREADS, SMEM_BYTES>>>(Q, K, V);
    fa_combine_kernel<<<NROWS * 4 / 256, 256>>>(O);
    fa_dummy<<<1, 32>>>();
    fa_dummy<<<1, 32>>>();
    fa_dummy<<<1, 32>>>();
}

// round 15
// speedup vs baseline: 1.9941x; 1.5393x over previous
#include <cuda_runtime.h>
#include <cuda_bf16.h>
#include <cuda_fp16.h>
#include <cstdint>
#include <math.h>

// Causal self-attention, B=4, S=4096, D=64, fp32.
// R15: QK^T = bf16 m16n8k16 x3 (Markidis). PV = fp16 m16n8k16 x1 with P
// packed in-register from the S c-frags (no smem roundtrip); V staged as
// half2 key-pairs. 4-way split-K + combine.

#define BB 4
#define SS 4096
#define DHH 64
#define BMM 64
#define NTHREADS 128
#define SPLITS 4
#define NROWS (BB * SS)

// smem words: KH [64][36]=2304, KL 2304, V half2 [64 dims][40]=2560, QF 4096.
#define OFF_K 0
#define OFF_V 4608
#define OFF_QF 7168
#define SMEM_FLOATS 11264
#define SMEM_BYTES (SMEM_FLOATS * 4)

__device__ float g_pO[SPLITS * NROWS * DHH];
__device__ float g_ml[SPLITS * NROWS * 2];

__device__ __forceinline__ float ex2a(float x) {
    float y; asm("ex2.approx.f32 %0,%1;" : "=f"(y) : "f"(x)); return y;
}
__device__ __forceinline__ void bfsplit(float v, float& hf, float& lf) {
    __nv_bfloat16 h = __float2bfloat16(v);
    hf = __bfloat162float(h);
    lf = v - hf;
}
__device__ __forceinline__ uint32_t packbf(float lo, float hi) {
    __nv_bfloat162 t = __floats2bfloat162_rn(lo, hi);
    return *(uint32_t*)&t;
}
__device__ __forceinline__ uint32_t packh2(float lo, float hi) {
    __half2 t = __floats2half2_rn(lo, hi);
    return *(uint32_t*)&t;
}

__device__ __forceinline__ void mma_bf16(float c[4], uint4 a,
                                         uint32_t b0, uint32_t b1) {
    asm("mma.sync.aligned.m16n8k16.row.col.f32.bf16.bf16.f32 "
        "{%0,%1,%2,%3},{%4,%5,%6,%7},{%8,%9},{%0,%1,%2,%3};"
        : "+f"(c[0]), "+f"(c[1]), "+f"(c[2]), "+f"(c[3])
        : "r"(a.x), "r"(a.y), "r"(a.z), "r"(a.w), "r"(b0), "r"(b1));
}
__device__ __forceinline__ void mma_f16(float c[4], uint4 a,
                                        uint32_t b0, uint32_t b1) {
    asm("mma.sync.aligned.m16n8k16.row.col.f32.f16.f16.f32 "
        "{%0,%1,%2,%3},{%4,%5,%6,%7},{%8,%9},{%0,%1,%2,%3};"
        : "+f"(c[0]), "+f"(c[1]), "+f"(c[2]), "+f"(c[3])
        : "r"(a.x), "r"(a.y), "r"(a.z), "r"(a.w), "r"(b0), "r"(b1));
}

__global__ __launch_bounds__(NTHREADS, 3)
void fa_mma_split(const float* __restrict__ Q, const float* __restrict__ K,
                  const float* __restrict__ V) {
    extern __shared__ float sm[];
    const int idx   = blockIdx.x;
    const int split = idx & (SPLITS - 1);
    const int rest  = idx >> 2;
    const int b     = rest & 3;
    const int qt    = (SS / BMM) - 1 - (rest >> 2);   // heavy q-tiles first
    const int tid   = threadIdx.x;
    const int wid   = tid >> 5;
    const int lane  = tid & 31;
    const int gg    = lane >> 2;
    const int c4    = lane & 3;
    const int r0 = qt * BMM + wid * 16 + gg;
    const int r1 = r0 + 8;
    const int hi16 = 16 * ((gg >> 2) & 1);   // V-layout mask term

    float* po  = g_pO + ((size_t)split * NROWS) * DHH;
    float* pml = g_ml + ((size_t)split * NROWS) * 2;
    const int rowg_cta = b * SS + qt * BMM;

    const int len = (qt + SPLITS) / SPLITS;
    const int t0  = split * len;
    const int t1  = min(t0 + len, qt + 1);

    if (t0 >= t1) {   // empty split: neutral partials
        for (int i = tid; i < BMM * DHH; i += NTHREADS)
            po[(size_t)(rowg_cta + (i >> 6)) * DHH + (i & 63)] = 0.f;
        if (tid < BMM) {
            pml[(size_t)(rowg_cta + tid) * 2 + 0] = -INFINITY;
            pml[(size_t)(rowg_cta + tid) * 2 + 1] = 0.f;
        }
        return;
    }

    // ---- stage Q raw into K-region scratch, build packed bf16 frag tables
    {
        const float4* qg4 = (const float4*)(Q + ((size_t)b * SS + qt * BMM) * DHH);
        float4* qs4 = (float4*)sm;
#pragma unroll
        for (int i = 0; i < 8; i++) qs4[i * NTHREADS + tid] = qg4[i * NTHREADS + tid];
        __syncthreads();
        const float qscale = 0.125f * 1.44269504088896f;  // 1/sqrt(64)*log2(e)
        const int lr0 = wid * 16 + gg, lr1 = lr0 + 8;
        uint32_t* qfh = (uint32_t*)(sm + OFF_QF) + wid * 1024;
        uint32_t* qfl = qfh + 512;
#pragma unroll
        for (int ks = 0; ks < 4; ks++) {
            int d0 = 16 * ks + 2 * c4;
            float h[8], l[8];
            bfsplit(sm[lr0 * 64 + d0]     * qscale, h[0], l[0]);
            bfsplit(sm[lr0 * 64 + d0 + 1] * qscale, h[1], l[1]);
            bfsplit(sm[lr1 * 64 + d0]     * qscale, h[2], l[2]);
            bfsplit(sm[lr1 * 64 + d0 + 1] * qscale, h[3], l[3]);
            bfsplit(sm[lr0 * 64 + d0 + 8] * qscale, h[4], l[4]);
            bfsplit(sm[lr0 * 64 + d0 + 9] * qscale, h[5], l[5]);
            bfsplit(sm[lr1 * 64 + d0 + 8] * qscale, h[6], l[6]);
            bfsplit(sm[lr1 * 64 + d0 + 9] * qscale, h[7], l[7]);
            uint4 ah = make_uint4(packbf(h[0], h[1]), packbf(h[2], h[3]),
                                  packbf(h[4], h[5]), packbf(h[6], h[7]));
            uint4 al = make_uint4(packbf(l[0], l[1]), packbf(l[2], l[3]),
                                  packbf(l[4], l[5]), packbf(l[6], l[7]));
            *(uint4*)&qfh[ks * 128 + lane * 4] = ah;
            *(uint4*)&qfl[ks * 128 + lane * 4] = al;
        }
        __syncthreads();   // scratch free; K staging may proceed
    }

    float o[8][4];
#pragma unroll
    for (int w = 0; w < 8; w++)
#pragma unroll
        for (int c = 0; c < 4; c++) o[w][c] = 0.f;
    float m0 = -INFINITY, m1 = -INFINITY, l0 = 0.f, l1 = 0.f;

    uint32_t* KHw = (uint32_t*)sm;          // stride 36 words/key
    uint32_t* KLw = KHw + 2304;
    uint32_t* Vw  = (uint32_t*)(sm + OFF_V); // half2 words, stride 40/dim

    for (int kt = t0; kt < t1; kt++) {
        const bool masked = (kt == qt);

        // ---- stage K: bf16 hi/lo split once, packed words, stride 36
        const float4* kg4 = (const float4*)(K + ((size_t)b * SS + kt * 64) * DHH);
        const float4* vg4 = (const float4*)(V + ((size_t)b * SS + kt * 64) * DHH);
#pragma unroll
        for (int i = 0; i < 8; i++) {
            int e = i * NTHREADS + tid;
            float4 kv = kg4[e];
            int n = e >> 4, dbase = (e & 15) << 2;
            int w0 = n * 36 + (dbase >> 1);
            float h0, lo0, h1, lo1, h2, lo2, h3, lo3;
            bfsplit(kv.x, h0, lo0); bfsplit(kv.y, h1, lo1);
            bfsplit(kv.z, h2, lo2); bfsplit(kv.w, h3, lo3);
            KHw[w0]     = packbf(h0, h1);
            KHw[w0 + 1] = packbf(h2, h3);
            KLw[w0]     = packbf(lo0, lo1);
            KLw[w0 + 1] = packbf(lo2, lo3);
        }
        // ---- stage V as half2 key-pairs: word(d, pair p) = h2(V[2p][d],V[2p+1][d])
        // column index c(p) = (p&3)*2 + ((p>>2)&1) + (p&~7), XOR mask by dim.
#pragma unroll
        for (int i = 0; i < 4; i++) {
            int e = i * NTHREADS + tid;           // 512 items
            int p  = e >> 4, dq = e & 15;
            float4 v0 = vg4[(2 * p) * 16 + dq];
            float4 v1 = vg4[(2 * p + 1) * 16 + dq];
            int cp = (p & 3) * 2 + ((p >> 2) & 1) + (p & ~7);
            float a0[4] = {v0.x, v0.y, v0.z, v0.w};
            float a1[4] = {v1.x, v1.y, v1.z, v1.w};
#pragma unroll
            for (int jj = 0; jj < 4; jj++) {
                int d = 4 * dq + jj;
                int msk = (16 * ((d >> 2) & 1)) ^ (2 * ((d >> 3) & 7));
                Vw[d * 40 + (cp ^ msk)] = packh2(a0[jj], a1[jj]);
            }
        }
        __syncthreads();

        // ---- S = Q K^T : bf16 k16 x 3 terms
        float s[8][4];
#pragma unroll
        for (int nn = 0; nn < 8; nn++)
            s[nn][0] = s[nn][1] = s[nn][2] = s[nn][3] = 0.f;
        const uint32_t* qfh = (const uint32_t*)(sm + OFF_QF) + wid * 1024;
        const uint32_t* qfl = qfh + 512;
#pragma unroll
        for (int ks = 0; ks < 4; ks++) {
            uint4 ah = *(const uint4*)&qfh[ks * 128 + lane * 4];
            uint4 al = *(const uint4*)&qfl[ks * 128 + lane * 4];
#pragma unroll
            for (int nn = 0; nn < 8; nn++) {
                int base = (nn * 8 + gg) * 36 + 8 * ks + c4;
                uint32_t bh0 = KHw[base], bh1 = KHw[base + 4];
                uint32_t bl0 = KLw[base], bl1 = KLw[base + 4];
                mma_bf16(s[nn], ah, bh0, bh1);
                mma_bf16(s[nn], al, bh0, bh1);
                mma_bf16(s[nn], ah, bl0, bl1);
            }
        }

        if (masked) {
#pragma unroll
            for (int nn = 0; nn < 8; nn++) {
                int kb = kt * 64 + nn * 8 + 2 * c4;
                if (kb     > r0) s[nn][0] = -1e30f;
                if (kb + 1 > r0) s[nn][1] = -1e30f;
                if (kb     > r1) s[nn][2] = -1e30f;
                if (kb + 1 > r1) s[nn][3] = -1e30f;
            }
        }

        // ---- online softmax (l summed from unrounded p; rn pack is unbiased)
        float x0 = s[0][0], x1 = s[0][2];
#pragma unroll
        for (int nn = 0; nn < 8; nn++) {
            x0 = fmaxf(x0, fmaxf(s[nn][0], s[nn][1]));
            x1 = fmaxf(x1, fmaxf(s[nn][2], s[nn][3]));
        }
        x0 = fmaxf(x0, __shfl_xor_sync(0xffffffffu, x0, 1));
        x0 = fmaxf(x0, __shfl_xor_sync(0xffffffffu, x0, 2));
        x1 = fmaxf(x1, __shfl_xor_sync(0xffffffffu, x1, 1));
        x1 = fmaxf(x1, __shfl_xor_sync(0xffffffffu, x1, 2));
        float nm0 = fmaxf(m0, x0), nm1 = fmaxf(m1, x1);
        float sc0 = ex2a(m0 - nm0), sc1 = ex2a(m1 - nm1);
        m0 = nm0; m1 = nm1;
        l0 *= sc0; l1 *= sc1;
        float u0 = 0.f, u1 = 0.f;
#pragma unroll
        for (int nn = 0; nn < 8; nn++) {
            s[nn][0] = ex2a(s[nn][0] - m0);
            s[nn][1] = ex2a(s[nn][1] - m0);
            s[nn][2] = ex2a(s[nn][2] - m1);
            s[nn][3] = ex2a(s[nn][3] - m1);
            u0 += s[nn][0] + s[nn][1];
            u1 += s[nn][2] + s[nn][3];
        }
        u0 += __shfl_xor_sync(0xffffffffu, u0, 1);
        u0 += __shfl_xor_sync(0xffffffffu, u0, 2);
        u1 += __shfl_xor_sync(0xffffffffu, u1, 1);
        u1 += __shfl_xor_sync(0xffffffffu, u1, 2);
        l0 += u0; l1 += u1;
#pragma unroll
        for (int w = 0; w < 8; w++) {
            o[w][0] *= sc0; o[w][1] *= sc0;
            o[w][2] *= sc1; o[w][3] *= sc1;
        }

        // ---- O += P V : fp16 k16, P packed IN-REGISTER from S c-frags
#pragma unroll
        for (int ks = 0; ks < 4; ks++) {
            uint4 a;
            a.x = packh2(s[2 * ks][0],     s[2 * ks][1]);       // row gg,  k 2c4..
            a.y = packh2(s[2 * ks][2],     s[2 * ks][3]);       // row gg+8
            a.z = packh2(s[2 * ks + 1][0], s[2 * ks + 1][1]);   // row gg,  k+8
            a.w = packh2(s[2 * ks + 1][2], s[2 * ks + 1][3]);   // row gg+8
#pragma unroll
            for (int w = 0; w < 8; w++) {
                int widx = (8 * w + gg) * 40
                         + (((8 * ks + 2 * c4) ^ (2 * w)) ^ hi16);
                uint2 bv = *(const uint2*)&Vw[widx];
                mma_f16(o[w], a, bv.x, bv.y);
            }
        }
        __syncthreads();   // K/V reads done before next tile's staging
    }

    // ---- write partials (unnormalized O + per-row m,l)
    const int g0 = b * SS + r0, g1 = b * SS + r1;
#pragma unroll
    for (int w = 0; w < 8; w++) {
        int col = w * 8 + 2 * c4;
        *(float2*)&po[(size_t)g0 * DHH + col] = make_float2(o[w][0], o[w][1]);
        *(float2*)&po[(size_t)g1 * DHH + col] = make_float2(o[w][2], o[w][3]);
    }
    if (c4 == 0) {
        pml[(size_t)g0 * 2 + 0] = m0; pml[(size_t)g0 * 2 + 1] = l0;
        pml[(size_t)g1 * 2 + 0] = m1; pml[(size_t)g1 * 2 + 1] = l1;
    }
}

__global__ __launch_bounds__(256)
void fa_combine_kernel(float* __restrict__ O) {
    const int gid  = blockIdx.x * 256 + threadIdx.x;
    const int part = gid & 3;
    const int row  = gid >> 2;

    float mv[SPLITS], lv[SPLITS];
#pragma unroll
    for (int s = 0; s < SPLITS; s++) {
        mv[s] = g_ml[((size_t)s * NROWS + row) * 2 + 0];
        lv[s] = g_ml[((size_t)s * NROWS + row) * 2 + 1];
    }
    float M = fmaxf(fmaxf(mv[0], mv[1]), fmaxf(mv[2], mv[3]));
    float w[SPLITS], L = 0.f;
#pragma unroll
    for (int s = 0; s < SPLITS; s++) {
        w[s] = ex2a(mv[s] - M);
        L += w[s] * lv[s];
    }
    const float inv = 1.f / L;

    float4 acc[4];
#pragma unroll
    for (int i = 0; i < 4; i++) acc[i] = make_float4(0.f, 0.f, 0.f, 0.f);
#pragma unroll
    for (int s = 0; s < SPLITS; s++) {
        const float4* p = (const float4*)(
            g_pO + ((size_t)s * NROWS + row) * DHH + part * 16);
        float ws = w[s];
#pragma unroll
        for (int i = 0; i < 4; i++) {
            float4 v = p[i];
            acc[i].x = fmaf(ws, v.x, acc[i].x);
            acc[i].y = fmaf(ws, v.y, acc[i].y);
            acc[i].z = fmaf(ws, v.z, acc[i].z);
            acc[i].w = fmaf(ws, v.w, acc[i].w);
        }
    }
    float4* out = (float4*)(O + (size_t)row * DHH + part * 16);
#pragma unroll
    for (int i = 0; i < 4; i++) {
        float4 v = acc[i];
        v.x *= inv; v.y *= inv; v.z *= inv; v.w *= inv;
        out[i] = v;
    }
}

extern "C" void kernel_launch(void* const* d_in, const int* in_sizes, int n_in,
                              void* d_out, int out_size) {
    const float* Q = (const float*)d_in[0];
    const float* K = (const float*)d_in[1];
    const float* V = (const float*)d_in[2];
    float* O = (float*)d_out;

    cudaFuncSetAttribute(fa_mma_split,
                         cudaFuncAttributeMaxDynamicSharedMemorySize, SMEM_BYTES);
    const int grid = SPLITS * BB * (SS / BMM);   // 1024 CTAs
    fa_mma_split<<<grid, NTHREADS, SMEM_BYTES>>>(Q, K, V);
    fa_combine_kernel<<<NROWS * 4 / 256, 256>>>(O);
}

// round 16
// speedup vs baseline: 2.3145x; 1.1606x over previous
#include <cuda_runtime.h>
#include <cuda_fp16.h>
#include <cstdint>
#include <math.h>

// Causal self-attention, B=4, S=4096, D=64, fp32.
// R16: QK^T = fp16 m16n8k16 x2 (Q split fp16 hi+lo, K fp16-rounded once).
// PV = fp16 m16n8k16 x1 with P packed in-register from S c-frags.
// 4-way split-K + combine.

#define BB 4
#define SS 4096
#define DHH 64
#define BMM 64
#define NTHREADS 128
#define SPLITS 4
#define NROWS (BB * SS)

// smem words: KH [64 keys][36] = 2304, V half2 [64 dims][40] = 2560,
// Q frag tables 4 warps x 1024 (hi 512 | lo 512) = 4096.
#define OFF_K 0
#define OFF_V 2304
#define OFF_QF 4864
#define SMEM_FLOATS 8960
#define SMEM_BYTES (SMEM_FLOATS * 4)

__device__ float g_pO[SPLITS * NROWS * DHH];
__device__ float g_ml[SPLITS * NROWS * 2];

__device__ __forceinline__ float ex2a(float x) {
    float y; asm("ex2.approx.f32 %0,%1;" : "=f"(y) : "f"(x)); return y;
}
__device__ __forceinline__ void hsplit(float v, float& hf, float& lf) {
    __half h = __float2half_rn(v);
    hf = __half2float(h);
    lf = v - hf;                    // exact in fp32
}
__device__ __forceinline__ uint32_t packh2(float lo, float hi) {
    __half2 t = __floats2half2_rn(lo, hi);
    return *(uint32_t*)&t;
}

__device__ __forceinline__ void mma_f16(float c[4], uint4 a,
                                        uint32_t b0, uint32_t b1) {
    asm("mma.sync.aligned.m16n8k16.row.col.f32.f16.f16.f32 "
        "{%0,%1,%2,%3},{%4,%5,%6,%7},{%8,%9},{%0,%1,%2,%3};"
        : "+f"(c[0]), "+f"(c[1]), "+f"(c[2]), "+f"(c[3])
        : "r"(a.x), "r"(a.y), "r"(a.z), "r"(a.w), "r"(b0), "r"(b1));
}

__global__ __launch_bounds__(NTHREADS, 4)
void fa_mma_split(const float* __restrict__ Q, const float* __restrict__ K,
                  const float* __restrict__ V) {
    extern __shared__ float sm[];
    const int idx   = blockIdx.x;
    const int split = idx & (SPLITS - 1);
    const int rest  = idx >> 2;
    const int b     = rest & 3;
    const int qt    = (SS / BMM) - 1 - (rest >> 2);   // heavy q-tiles first
    const int tid   = threadIdx.x;
    const int wid   = tid >> 5;
    const int lane  = tid & 31;
    const int gg    = lane >> 2;
    const int c4    = lane & 3;
    const int r0 = qt * BMM + wid * 16 + gg;
    const int r1 = r0 + 8;
    const int hi16 = 16 * ((gg >> 2) & 1);   // V-layout mask term

    float* po  = g_pO + ((size_t)split * NROWS) * DHH;
    float* pml = g_ml + ((size_t)split * NROWS) * 2;
    const int rowg_cta = b * SS + qt * BMM;

    const int len = (qt + SPLITS) / SPLITS;
    const int t0  = split * len;
    const int t1  = min(t0 + len, qt + 1);

    if (t0 >= t1) {   // empty split: neutral partials
        for (int i = tid; i < BMM * DHH; i += NTHREADS)
            po[(size_t)(rowg_cta + (i >> 6)) * DHH + (i & 63)] = 0.f;
        if (tid < BMM) {
            pml[(size_t)(rowg_cta + tid) * 2 + 0] = -INFINITY;
            pml[(size_t)(rowg_cta + tid) * 2 + 1] = 0.f;
        }
        return;
    }

    // ---- stage Q raw into smem scratch, build packed fp16 hi/lo frag tables
    {
        const float4* qg4 = (const float4*)(Q + ((size_t)b * SS + qt * BMM) * DHH);
        float4* qs4 = (float4*)sm;
#pragma unroll
        for (int i = 0; i < 8; i++) qs4[i * NTHREADS + tid] = qg4[i * NTHREADS + tid];
        __syncthreads();
        const float qscale = 0.125f * 1.44269504088896f;  // 1/sqrt(64)*log2(e)
        const int lr0 = wid * 16 + gg, lr1 = lr0 + 8;
        uint32_t* qfh = (uint32_t*)(sm + OFF_QF) + wid * 1024;
        uint32_t* qfl = qfh + 512;
#pragma unroll
        for (int ks = 0; ks < 4; ks++) {
            int d0 = 16 * ks + 2 * c4;
            float h[8], l[8];
            hsplit(sm[lr0 * 64 + d0]     * qscale, h[0], l[0]);
            hsplit(sm[lr0 * 64 + d0 + 1] * qscale, h[1], l[1]);
            hsplit(sm[lr1 * 64 + d0]     * qscale, h[2], l[2]);
            hsplit(sm[lr1 * 64 + d0 + 1] * qscale, h[3], l[3]);
            hsplit(sm[lr0 * 64 + d0 + 8] * qscale, h[4], l[4]);
            hsplit(sm[lr0 * 64 + d0 + 9] * qscale, h[5], l[5]);
            hsplit(sm[lr1 * 64 + d0 + 8] * qscale, h[6], l[6]);
            hsplit(sm[lr1 * 64 + d0 + 9] * qscale, h[7], l[7]);
            uint4 ah = make_uint4(packh2(h[0], h[1]), packh2(h[2], h[3]),
                                  packh2(h[4], h[5]), packh2(h[6], h[7]));
            uint4 al = make_uint4(packh2(l[0], l[1]), packh2(l[2], l[3]),
                                  packh2(l[4], l[5]), packh2(l[6], l[7]));
            *(uint4*)&qfh[ks * 128 + lane * 4] = ah;
            *(uint4*)&qfl[ks * 128 + lane * 4] = al;
        }
        __syncthreads();   // scratch free; K/V staging may proceed
    }

    float o[8][4];
#pragma unroll
    for (int w = 0; w < 8; w++)
#pragma unroll
        for (int c = 0; c < 4; c++) o[w][c] = 0.f;
    float m0 = -INFINITY, m1 = -INFINITY, l0 = 0.f, l1 = 0.f;

    uint32_t* KHw = (uint32_t*)sm;           // stride 36 words/key
    uint32_t* Vw  = (uint32_t*)(sm + OFF_V); // half2 words, stride 40/dim

    for (int kt = t0; kt < t1; kt++) {
        const bool masked = (kt == qt);

        // ---- stage K: fp16-rounded once, packed words, stride 36
        const float4* kg4 = (const float4*)(K + ((size_t)b * SS + kt * 64) * DHH);
        const float4* vg4 = (const float4*)(V + ((size_t)b * SS + kt * 64) * DHH);
#pragma unroll
        for (int i = 0; i < 8; i++) {
            int e = i * NTHREADS + tid;
            float4 kv = kg4[e];
            int n = e >> 4, dbase = (e & 15) << 2;
            int w0 = n * 36 + (dbase >> 1);
            KHw[w0]     = packh2(kv.x, kv.y);
            KHw[w0 + 1] = packh2(kv.z, kv.w);
        }
        // ---- stage V as half2 key-pairs (layout as R15)
#pragma unroll
        for (int i = 0; i < 4; i++) {
            int e = i * NTHREADS + tid;           // 512 items
            int p  = e >> 4, dq = e & 15;
            float4 v0 = vg4[(2 * p) * 16 + dq];
            float4 v1 = vg4[(2 * p + 1) * 16 + dq];
            int cp = (p & 3) * 2 + ((p >> 2) & 1) + (p & ~7);
            float a0[4] = {v0.x, v0.y, v0.z, v0.w};
            float a1[4] = {v1.x, v1.y, v1.z, v1.w};
#pragma unroll
            for (int jj = 0; jj < 4; jj++) {
                int d = 4 * dq + jj;
                int msk = (16 * ((d >> 2) & 1)) ^ (2 * ((d >> 3) & 7));
                Vw[d * 40 + (cp ^ msk)] = packh2(a0[jj], a1[jj]);
            }
        }
        __syncthreads();

        // ---- S = Q K^T : fp16 k16 x 2 terms (Qh*Kh + Ql*Kh)
        float s[8][4];
#pragma unroll
        for (int nn = 0; nn < 8; nn++)
            s[nn][0] = s[nn][1] = s[nn][2] = s[nn][3] = 0.f;
        const uint32_t* qfh = (const uint32_t*)(sm + OFF_QF) + wid * 1024;
        const uint32_t* qfl = qfh + 512;
#pragma unroll
        for (int ks = 0; ks < 4; ks++) {
            uint4 ah = *(const uint4*)&qfh[ks * 128 + lane * 4];
            uint4 al = *(const uint4*)&qfl[ks * 128 + lane * 4];
#pragma unroll
            for (int nn = 0; nn < 8; nn++) {
                int base = (nn * 8 + gg) * 36 + 8 * ks + c4;
                uint32_t bh0 = KHw[base], bh1 = KHw[base + 4];
                mma_f16(s[nn], ah, bh0, bh1);
                mma_f16(s[nn], al, bh0, bh1);
            }
        }

        if (masked) {
#pragma unroll
            for (int nn = 0; nn < 8; nn++) {
                int kb = kt * 64 + nn * 8 + 2 * c4;
                if (kb     > r0) s[nn][0] = -1e30f;
                if (kb + 1 > r0) s[nn][1] = -1e30f;
                if (kb     > r1) s[nn][2] = -1e30f;
                if (kb + 1 > r1) s[nn][3] = -1e30f;
            }
        }

        // ---- online softmax
        float x0 = s[0][0], x1 = s[0][2];
#pragma unroll
        for (int nn = 0; nn < 8; nn++) {
            x0 = fmaxf(x0, fmaxf(s[nn][0], s[nn][1]));
            x1 = fmaxf(x1, fmaxf(s[nn][2], s[nn][3]));
        }
        x0 = fmaxf(x0, __shfl_xor_sync(0xffffffffu, x0, 1));
        x0 = fmaxf(x0, __shfl_xor_sync(0xffffffffu, x0, 2));
        x1 = fmaxf(x1, __shfl_xor_sync(0xffffffffu, x1, 1));
        x1 = fmaxf(x1, __shfl_xor_sync(0xffffffffu, x1, 2));
        float nm0 = fmaxf(m0, x0), nm1 = fmaxf(m1, x1);
        float sc0 = ex2a(m0 - nm0), sc1 = ex2a(m1 - nm1);
        m0 = nm0; m1 = nm1;
        l0 *= sc0; l1 *= sc1;
        float u0 = 0.f, u1 = 0.f;
#pragma unroll
        for (int nn = 0; nn < 8; nn++) {
            s[nn][0] = ex2a(s[nn][0] - m0);
            s[nn][1] = ex2a(s[nn][1] - m0);
            s[nn][2] = ex2a(s[nn][2] - m1);
            s[nn][3] = ex2a(s[nn][3] - m1);
            u0 += s[nn][0] + s[nn][1];
            u1 += s[nn][2] + s[nn][3];
        }
        u0 += __shfl_xor_sync(0xffffffffu, u0, 1);
        u0 += __shfl_xor_sync(0xffffffffu, u0, 2);
        u1 += __shfl_xor_sync(0xffffffffu, u1, 1);
        u1 += __shfl_xor_sync(0xffffffffu, u1, 2);
        l0 += u0; l1 += u1;
#pragma unroll
        for (int w = 0; w < 8; w++) {
            o[w][0] *= sc0; o[w][1] *= sc0;
            o[w][2] *= sc1; o[w][3] *= sc1;
        }

        // ---- O += P V : fp16 k16, P packed in-register from S c-frags
#pragma unroll
        for (int ks = 0; ks < 4; ks++) {
            uint4 a;
            a.x = packh2(s[2 * ks][0],     s[2 * ks][1]);
            a.y = packh2(s[2 * ks][2],     s[2 * ks][3]);
            a.z = packh2(s[2 * ks + 1][0], s[2 * ks + 1][1]);
            a.w = packh2(s[2 * ks + 1][2], s[2 * ks + 1][3]);
#pragma unroll
            for (int w = 0; w < 8; w++) {
                int widx = (8 * w + gg) * 40
                         + (((8 * ks + 2 * c4) ^ (2 * w)) ^ hi16);
                uint2 bv = *(const uint2*)&Vw[widx];
                mma_f16(o[w], a, bv.x, bv.y);
            }
        }
        __syncthreads();   // K/V reads done before next tile's staging
    }

    // ---- write partials (unnormalized O + per-row m,l)
    const int g0 = b * SS + r0, g1 = b * SS + r1;
#pragma unroll
    for (int w = 0; w < 8; w++) {
        int col = w * 8 + 2 * c4;
        *(float2*)&po[(size_t)g0 * DHH + col] = make_float2(o[w][0], o[w][1]);
        *(float2*)&po[(size_t)g1 * DHH + col] = make_float2(o[w][2], o[w][3]);
    }
    if (c4 == 0) {
        pml[(size_t)g0 * 2 + 0] = m0; pml[(size_t)g0 * 2 + 1] = l0;
        pml[(size_t)g1 * 2 + 0] = m1; pml[(size_t)g1 * 2 + 1] = l1;
    }
}

__global__ __launch_bounds__(256)
void fa_combine_kernel(float* __restrict__ O) {
    const int gid  = blockIdx.x * 256 + threadIdx.x;
    const int part = gid & 3;
    const int row  = gid >> 2;

    float mv[SPLITS], lv[SPLITS];
#pragma unroll
    for (int s = 0; s < SPLITS; s++) {
        mv[s] = g_ml[((size_t)s * NROWS + row) * 2 + 0];
        lv[s] = g_ml[((size_t)s * NROWS + row) * 2 + 1];
    }
    float M = fmaxf(fmaxf(mv[0], mv[1]), fmaxf(mv[2], mv[3]));
    float w[SPLITS], L = 0.f;
#pragma unroll
    for (int s = 0; s < SPLITS; s++) {
        w[s] = ex2a(mv[s] - M);
        L += w[s] * lv[s];
    }
    const float inv = 1.f / L;

    float4 acc[4];
#pragma unroll
    for (int i = 0; i < 4; i++) acc[i] = make_float4(0.f, 0.f, 0.f, 0.f);
#pragma unroll
    for (int s = 0; s < SPLITS; s++) {
        const float4* p = (const float4*)(
            g_pO + ((size_t)s * NROWS + row) * DHH + part * 16);
        float ws = w[s];
#pragma unroll
        for (int i = 0; i < 4; i++) {
            float4 v = p[i];
            acc[i].x = fmaf(ws, v.x, acc[i].x);
            acc[i].y = fmaf(ws, v.y, acc[i].y);
            acc[i].z = fmaf(ws, v.z, acc[i].z);
            acc[i].w = fmaf(ws, v.w, acc[i].w);
        }
    }
    float4* out = (float4*)(O + (size_t)row * DHH + part * 16);
#pragma unroll
    for (int i = 0; i < 4; i++) {
        float4 v = acc[i];
        v.x *= inv; v.y *= inv; v.z *= inv; v.w *= inv;
        out[i] = v;
    }
}

extern "C" void kernel_launch(void* const* d_in, const int* in_sizes, int n_in,
                              void* d_out, int out_size) {
    const float* Q = (const float*)d_in[0];
    const float* K = (const float*)d_in[1];
    const float* V = (const float*)d_in[2];
    float* O = (float*)d_out;

    cudaFuncSetAttribute(fa_mma_split,
                         cudaFuncAttributeMaxDynamicSharedMemorySize, SMEM_BYTES);
    const int grid = SPLITS * BB * (SS / BMM);   // 1024 CTAs
    fa_mma_split<<<grid, NTHREADS, SMEM_BYTES>>>(Q, K, V);
    fa_combine_kernel<<<NROWS * 4 / 256, 256>>>(O);
}

// round 17
// speedup vs baseline: 2.7117x; 1.1716x over previous
#include <cuda_runtime.h>
#include <cuda_fp16.h>
#include <cstdint>
#include <math.h>

// Causal self-attention, B=4, S=4096, D=64, fp32.
// R17: QK^T = fp16 m16n8k16 x1 (Q,K fp16-rounded; iid rounding noise cancels
// through softmax). PV = fp16 m16n8k16 x1, P packed in-register from S
// c-frags. 4-way split-K + wide-grid combine.

#define BB 4
#define SS 4096
#define DHH 64
#define BMM 64
#define NTHREADS 128
#define SPLITS 4
#define NROWS (BB * SS)

// smem words: KH [64 keys][36] = 2304, V half2 [64 dims][40] = 2560,
// Q frag tables 4 warps x 512 = 2048.
#define OFF_K 0
#define OFF_V 2304
#define OFF_QF 4864
#define SMEM_FLOATS 6912
#define SMEM_BYTES (SMEM_FLOATS * 4)

__device__ float g_pO[SPLITS * NROWS * DHH];
__device__ float g_ml[SPLITS * NROWS * 2];

__device__ __forceinline__ float ex2a(float x) {
    float y; asm("ex2.approx.f32 %0,%1;" : "=f"(y) : "f"(x)); return y;
}
__device__ __forceinline__ uint32_t packh2(float lo, float hi) {
    __half2 t = __floats2half2_rn(lo, hi);
    return *(uint32_t*)&t;
}

__device__ __forceinline__ void mma_f16(float c[4], uint4 a,
                                        uint32_t b0, uint32_t b1) {
    asm("mma.sync.aligned.m16n8k16.row.col.f32.f16.f16.f32 "
        "{%0,%1,%2,%3},{%4,%5,%6,%7},{%8,%9},{%0,%1,%2,%3};"
        : "+f"(c[0]), "+f"(c[1]), "+f"(c[2]), "+f"(c[3])
        : "r"(a.x), "r"(a.y), "r"(a.z), "r"(a.w), "r"(b0), "r"(b1));
}

__global__ __launch_bounds__(NTHREADS, 4)
void fa_mma_split(const float* __restrict__ Q, const float* __restrict__ K,
                  const float* __restrict__ V) {
    extern __shared__ float sm[];
    const int idx   = blockIdx.x;
    const int split = idx & (SPLITS - 1);
    const int rest  = idx >> 2;
    const int b     = rest & 3;
    const int qt    = (SS / BMM) - 1 - (rest >> 2);   // heavy q-tiles first
    const int tid   = threadIdx.x;
    const int wid   = tid >> 5;
    const int lane  = tid & 31;
    const int gg    = lane >> 2;
    const int c4    = lane & 3;
    const int r0 = qt * BMM + wid * 16 + gg;
    const int r1 = r0 + 8;
    const int hi16 = 16 * ((gg >> 2) & 1);   // V-layout mask term

    float* po  = g_pO + ((size_t)split * NROWS) * DHH;
    float* pml = g_ml + ((size_t)split * NROWS) * 2;
    const int rowg_cta = b * SS + qt * BMM;

    const int len = (qt + SPLITS) / SPLITS;
    const int t0  = split * len;
    const int t1  = min(t0 + len, qt + 1);

    if (t0 >= t1) {   // empty split: neutral partials
        for (int i = tid; i < BMM * DHH; i += NTHREADS)
            po[(size_t)(rowg_cta + (i >> 6)) * DHH + (i & 63)] = 0.f;
        if (tid < BMM) {
            pml[(size_t)(rowg_cta + tid) * 2 + 0] = -INFINITY;
            pml[(size_t)(rowg_cta + tid) * 2 + 1] = 0.f;
        }
        return;
    }

    // ---- stage Q raw into smem scratch, build packed fp16 frag table
    {
        const float4* qg4 = (const float4*)(Q + ((size_t)b * SS + qt * BMM) * DHH);
        float4* qs4 = (float4*)sm;
#pragma unroll
        for (int i = 0; i < 8; i++) qs4[i * NTHREADS + tid] = qg4[i * NTHREADS + tid];
        __syncthreads();
        const float qscale = 0.125f * 1.44269504088896f;  // 1/sqrt(64)*log2(e)
        const int lr0 = wid * 16 + gg, lr1 = lr0 + 8;
        uint32_t* qfh = (uint32_t*)(sm + OFF_QF) + wid * 512;
#pragma unroll
        for (int ks = 0; ks < 4; ks++) {
            int d0 = 16 * ks + 2 * c4;
            uint4 ah;
            ah.x = packh2(sm[lr0 * 64 + d0]     * qscale,
                          sm[lr0 * 64 + d0 + 1] * qscale);
            ah.y = packh2(sm[lr1 * 64 + d0]     * qscale,
                          sm[lr1 * 64 + d0 + 1] * qscale);
            ah.z = packh2(sm[lr0 * 64 + d0 + 8] * qscale,
                          sm[lr0 * 64 + d0 + 9] * qscale);
            ah.w = packh2(sm[lr1 * 64 + d0 + 8] * qscale,
                          sm[lr1 * 64 + d0 + 9] * qscale);
            *(uint4*)&qfh[ks * 128 + lane * 4] = ah;
        }
        __syncthreads();   // scratch free; K/V staging may proceed
    }

    float o[8][4];
#pragma unroll
    for (int w = 0; w < 8; w++)
#pragma unroll
        for (int c = 0; c < 4; c++) o[w][c] = 0.f;
    float m0 = -INFINITY, m1 = -INFINITY, l0 = 0.f, l1 = 0.f;

    uint32_t* KHw = (uint32_t*)sm;           // stride 36 words/key
    uint32_t* Vw  = (uint32_t*)(sm + OFF_V); // half2 words, stride 40/dim

    for (int kt = t0; kt < t1; kt++) {
        const bool masked = (kt == qt);

        // ---- stage K: fp16-rounded once, packed words, stride 36
        const float4* kg4 = (const float4*)(K + ((size_t)b * SS + kt * 64) * DHH);
        const float4* vg4 = (const float4*)(V + ((size_t)b * SS + kt * 64) * DHH);
#pragma unroll
        for (int i = 0; i < 8; i++) {
            int e = i * NTHREADS + tid;
            float4 kv = kg4[e];
            int n = e >> 4, dbase = (e & 15) << 2;
            int w0 = n * 36 + (dbase >> 1);
            KHw[w0]     = packh2(kv.x, kv.y);
            KHw[w0 + 1] = packh2(kv.z, kv.w);
        }
        // ---- stage V as half2 key-pairs (layout as R15)
#pragma unroll
        for (int i = 0; i < 4; i++) {
            int e = i * NTHREADS + tid;           // 512 items
            int p  = e >> 4, dq = e & 15;
            float4 v0 = vg4[(2 * p) * 16 + dq];
            float4 v1 = vg4[(2 * p + 1) * 16 + dq];
            int cp = (p & 3) * 2 + ((p >> 2) & 1) + (p & ~7);
            float a0[4] = {v0.x, v0.y, v0.z, v0.w};
            float a1[4] = {v1.x, v1.y, v1.z, v1.w};
#pragma unroll
            for (int jj = 0; jj < 4; jj++) {
                int d = 4 * dq + jj;
                int msk = (16 * ((d >> 2) & 1)) ^ (2 * ((d >> 3) & 7));
                Vw[d * 40 + (cp ^ msk)] = packh2(a0[jj], a1[jj]);
            }
        }
        __syncthreads();

        // ---- S = Q K^T : fp16 k16 x 1 term
        float s[8][4];
#pragma unroll
        for (int nn = 0; nn < 8; nn++)
            s[nn][0] = s[nn][1] = s[nn][2] = s[nn][3] = 0.f;
        const uint32_t* qfh = (const uint32_t*)(sm + OFF_QF) + wid * 512;
#pragma unroll
        for (int ks = 0; ks < 4; ks++) {
            uint4 ah = *(const uint4*)&qfh[ks * 128 + lane * 4];
#pragma unroll
            for (int nn = 0; nn < 8; nn++) {
                int base = (nn * 8 + gg) * 36 + 8 * ks + c4;
                mma_f16(s[nn], ah, KHw[base], KHw[base + 4]);
            }
        }

        if (masked) {
#pragma unroll
            for (int nn = 0; nn < 8; nn++) {
                int kb = kt * 64 + nn * 8 + 2 * c4;
                if (kb     > r0) s[nn][0] = -1e30f;
                if (kb + 1 > r0) s[nn][1] = -1e30f;
                if (kb     > r1) s[nn][2] = -1e30f;
                if (kb + 1 > r1) s[nn][3] = -1e30f;
            }
        }

        // ---- online softmax
        float x0 = s[0][0], x1 = s[0][2];
#pragma unroll
        for (int nn = 0; nn < 8; nn++) {
            x0 = fmaxf(x0, fmaxf(s[nn][0], s[nn][1]));
            x1 = fmaxf(x1, fmaxf(s[nn][2], s[nn][3]));
        }
        x0 = fmaxf(x0, __shfl_xor_sync(0xffffffffu, x0, 1));
        x0 = fmaxf(x0, __shfl_xor_sync(0xffffffffu, x0, 2));
        x1 = fmaxf(x1, __shfl_xor_sync(0xffffffffu, x1, 1));
        x1 = fmaxf(x1, __shfl_xor_sync(0xffffffffu, x1, 2));
        float nm0 = fmaxf(m0, x0), nm1 = fmaxf(m1, x1);
        float sc0 = ex2a(m0 - nm0), sc1 = ex2a(m1 - nm1);
        m0 = nm0; m1 = nm1;
        l0 *= sc0; l1 *= sc1;
        float u0 = 0.f, u1 = 0.f;
#pragma unroll
        for (int nn = 0; nn < 8; nn++) {
            s[nn][0] = ex2a(s[nn][0] - m0);
            s[nn][1] = ex2a(s[nn][1] - m0);
            s[nn][2] = ex2a(s[nn][2] - m1);
            s[nn][3] = ex2a(s[nn][3] - m1);
            u0 += s[nn][0] + s[nn][1];
            u1 += s[nn][2] + s[nn][3];
        }
        u0 += __shfl_xor_sync(0xffffffffu, u0, 1);
        u0 += __shfl_xor_sync(0xffffffffu, u0, 2);
        u1 += __shfl_xor_sync(0xffffffffu, u1, 1);
        u1 += __shfl_xor_sync(0xffffffffu, u1, 2);
        l0 += u0; l1 += u1;
#pragma unroll
        for (int w = 0; w < 8; w++) {
            o[w][0] *= sc0; o[w][1] *= sc0;
            o[w][2] *= sc1; o[w][3] *= sc1;
        }

        // ---- O += P V : fp16 k16, P packed in-register from S c-frags
#pragma unroll
        for (int ks = 0; ks < 4; ks++) {
            uint4 a;
            a.x = packh2(s[2 * ks][0],     s[2 * ks][1]);
            a.y = packh2(s[2 * ks][2],     s[2 * ks][3]);
            a.z = packh2(s[2 * ks + 1][0], s[2 * ks + 1][1]);
            a.w = packh2(s[2 * ks + 1][2], s[2 * ks + 1][3]);
#pragma unroll
            for (int w = 0; w < 8; w++) {
                int widx = (8 * w + gg) * 40
                         + (((8 * ks + 2 * c4) ^ (2 * w)) ^ hi16);
                uint2 bv = *(const uint2*)&Vw[widx];
                mma_f16(o[w], a, bv.x, bv.y);
            }
        }
        __syncthreads();   // K/V reads done before next tile's staging
    }

    // ---- write partials (unnormalized O + per-row m,l)
    const int g0 = b * SS + r0, g1 = b * SS + r1;
#pragma unroll
    for (int w = 0; w < 8; w++) {
        int col = w * 8 + 2 * c4;
        *(float2*)&po[(size_t)g0 * DHH + col] = make_float2(o[w][0], o[w][1]);
        *(float2*)&po[(size_t)g1 * DHH + col] = make_float2(o[w][2], o[w][3]);
    }
    if (c4 == 0) {
        pml[(size_t)g0 * 2 + 0] = m0; pml[(size_t)g0 * 2 + 1] = l0;
        pml[(size_t)g1 * 2 + 0] = m1; pml[(size_t)g1 * 2 + 1] = l1;
    }
}

// Wide-grid combine: 1 thread per (row, 4 dims) -> 262144 threads.
__global__ __launch_bounds__(256)
void fa_combine_kernel(float* __restrict__ O) {
    const int gid  = blockIdx.x * 256 + threadIdx.x;   // NROWS * 16
    const int part = gid & 15;                         // 4 dims each
    const int row  = gid >> 4;

    float mv[SPLITS], lv[SPLITS];
#pragma unroll
    for (int s = 0; s < SPLITS; s++) {
        mv[s] = g_ml[((size_t)s * NROWS + row) * 2 + 0];
        lv[s] = g_ml[((size_t)s * NROWS + row) * 2 + 1];
    }
    float M = fmaxf(fmaxf(mv[0], mv[1]), fmaxf(mv[2], mv[3]));
    float w[SPLITS], L = 0.f;
#pragma unroll
    for (int s = 0; s < SPLITS; s++) {
        w[s] = ex2a(mv[s] - M);
        L += w[s] * lv[s];
    }
    const float inv = 1.f / L;

    float4 acc = make_float4(0.f, 0.f, 0.f, 0.f);
#pragma unroll
    for (int s = 0; s < SPLITS; s++) {
        float4 v = *(const float4*)(
            g_pO + ((size_t)s * NROWS + row) * DHH + part * 4);
        float ws = w[s];
        acc.x = fmaf(ws, v.x, acc.x);
        acc.y = fmaf(ws, v.y, acc.y);
        acc.z = fmaf(ws, v.z, acc.z);
        acc.w = fmaf(ws, v.w, acc.w);
    }
    acc.x *= inv; acc.y *= inv; acc.z *= inv; acc.w *= inv;
    *(float4*)(O + (size_t)row * DHH + part * 4) = acc;
}

extern "C" void kernel_launch(void* const* d_in, const int* in_sizes, int n_in,
                              void* d_out, int out_size) {
    const float* Q = (const float*)d_in[0];
    const float* K = (const float*)d_in[1];
    const float* V = (const float*)d_in[2];
    float* O = (float*)d_out;

    cudaFuncSetAttribute(fa_mma_split,
                         cudaFuncAttributeMaxDynamicSharedMemorySize, SMEM_BYTES);
    const int grid = SPLITS * BB * (SS / BMM);   // 1024 CTAs
    fa_mma_split<<<grid, NTHREADS, SMEM_BYTES>>>(Q, K, V);
    fa_combine_kernel<<<NROWS * 16 / 256, 256>>>(O);
}